// round 7
// baseline (speedup 1.0000x reference)
#include <cuda_runtime.h>
#include <math.h>

// ---------------- packed f32x2 helpers (sm_103a FFMA2 path) ----------------
typedef unsigned long long u64t;
__device__ __forceinline__ u64t pack2f(float lo, float hi) {
    u64t r;
    asm("mov.b64 %0, {%1, %2};" : "=l"(r)
        : "r"(__float_as_uint(lo)), "r"(__float_as_uint(hi)));
    return r;
}
__device__ __forceinline__ void ffma2(u64t& d, u64t a, u64t b) {
    asm("fma.rn.f32x2 %0, %1, %2, %0;" : "+l"(d) : "l"(a), "l"(b));
}
__device__ __forceinline__ void unpack2f(u64t v, float& lo, float& hi) {
    unsigned ulo, uhi;
    asm("mov.b64 {%0, %1}, %2;" : "=r"(ulo), "=r"(uhi) : "l"(v));
    lo = __uint_as_float(ulo);
    hi = __uint_as_float(uhi);
}

// ---------------- persistent device scratch (no allocations allowed) ----------------
__device__ float  g_buf0[16u*16u*64u*64u*64u];   // conv00 out (raw)   268MB
__device__ float  g_buf1[16u*32u*32u*32u*32u];   // conv0  out (raw)    67MB
__device__ float  g_buf2[16u*64u*16u*16u*16u];   // conv1  out (raw)  16.8MB
__device__ float  g_buf3[16u*64u*8u*8u*8u];      // conv2  out (raw)   2.1MB
__device__ float  g_buf4[16u*64u*4u*4u*4u];      // conv3  out (raw)  0.26MB
__device__ double g_stats[480];                  // per-stage [sum|sumsq]
__device__ float  g_scale[5*64];                 // BN apply scale
__device__ float  g_shift[5*64];                 // BN apply shift
__device__ float  g_theta[16*12];                // theta[:, :3, :]
__device__ float  g_wT0[32*16*27];               // w0 oc-major (13824)
__device__ float  g_wT1[64*32*27];               // w1 oc-major (55296)
__device__ float  g_wT2[64*64*27];               // w2 oc-major (110592)

// ---------------- utility kernels ----------------
__global__ void zero_stats_kernel(double* s) {
    int i = threadIdx.x;
    if (i < 480) s[i] = 0.0;
}

__global__ void finalize_kernel(const double* __restrict__ stats,
                                const float* __restrict__ g, const float* __restrict__ be,
                                float* __restrict__ sc, float* __restrict__ sh,
                                int C, double invN) {
    int c = threadIdx.x;
    if (c < C) {
        double mean = stats[c] * invN;
        double var  = stats[C + c] * invN - mean * mean;
        float a = g[c] * (float)(1.0 / sqrt(var + 1e-5));
        sc[c] = a;
        sh[c] = be[c] - (float)mean * a;
    }
}

// weight transpose: w[oc][icr] -> wT[icr][oc]  (icr = ic*27 + k9*3 + kw)
__global__ void transpose_w_kernel(const float* __restrict__ w, float* __restrict__ wT,
                                   int cin27, int cout) {
    int i = blockIdx.x * 256 + threadIdx.x;
    if (i < cin27 * cout) {
        int oc = i % cout, icr = i / cout;
        wT[i] = w[oc * cin27 + icr];
    }
}

// ---------------- conv00 v2: 1->16 ch, stride 1, pad 1, 64^3, FFMA2 ----------------
__global__ void __launch_bounds__(128) conv00_v2(
    const float* __restrict__ x, const float* __restrict__ w,
    const float* __restrict__ bias, float* __restrict__ out,
    double* __restrict__ stats) {
    __shared__ float sIn[1000];   // 10^3
    __shared__ float sWd[864];    // 27 * 16 oc * 2 (duplicated)

    int tid = threadIdx.x;
    int b = blockIdx.y;
    int t = blockIdx.x;
    int tz = t >> 6, ty = (t >> 3) & 7, tx = t & 7;

    for (int i = tid; i < 1000; i += 128) {
        int iz = i / 100, iy = (i / 10) % 10, ix = i % 10;
        int gz = tz * 8 - 1 + iz, gy = ty * 8 - 1 + iy, gx = tx * 8 - 1 + ix;
        float v = 0.f;
        if ((unsigned)gz < 64u && (unsigned)gy < 64u && (unsigned)gx < 64u)
            v = x[((b * 64 + gz) * 64 + gy) * 64 + gx];
        sIn[i] = v;
    }
    for (int i = tid; i < 432; i += 128) {
        int k = i >> 4, oc = i & 15;
        float wv = w[oc * 27 + k];
        sWd[k * 32 + oc * 2]     = wv;
        sWd[k * 32 + oc * 2 + 1] = wv;
    }
    __syncthreads();

    int sz = tid >> 4, sy = (tid >> 1) & 7, sx = tid & 1;

    u64t acc[16][2];
#pragma unroll
    for (int oc = 0; oc < 16; oc++) { acc[oc][0] = 0ULL; acc[oc][1] = 0ULL; }

#pragma unroll
    for (int kd = 0; kd < 3; kd++)
#pragma unroll
        for (int kh = 0; kh < 3; kh++) {
            int base = (sz + kd) * 100 + (sy + kh) * 10 + sx * 4;
            float i0 = sIn[base], i1 = sIn[base + 1], i2 = sIn[base + 2];
            float i3 = sIn[base + 3], i4 = sIn[base + 4], i5 = sIn[base + 5];
            u64t P[5];
            P[0] = pack2f(i0, i1); P[1] = pack2f(i1, i2); P[2] = pack2f(i2, i3);
            P[3] = pack2f(i3, i4); P[4] = pack2f(i4, i5);
            int k9 = kd * 3 + kh;
#pragma unroll
            for (int kw = 0; kw < 3; kw++) {
                const u64t* wrow =
                    reinterpret_cast<const u64t*>(&sWd[(k9 * 3 + kw) * 32]);
#pragma unroll
                for (int oc = 0; oc < 16; oc++) {
                    u64t wp = wrow[oc];
                    ffma2(acc[oc][0], P[kw], wp);
                    ffma2(acc[oc][1], P[kw + 2], wp);
                }
            }
        }

    int gz = tz * 8 + sz, gy = ty * 8 + sy, gx = tx * 8 + sx * 4;
#pragma unroll 1
    for (int oc = 0; oc < 16; oc++) {
        float a0, a1, a2, a3;
        unpack2f(acc[oc][0], a0, a1);
        unpack2f(acc[oc][1], a2, a3);
        float bb = bias[oc];
        a0 += bb; a1 += bb; a2 += bb; a3 += bb;
        *reinterpret_cast<float4*>(&out[(((b * 16 + oc) * 64 + gz) * 64 + gy) * 64 + gx]) =
            make_float4(a0, a1, a2, a3);

        float s = a0 + a1 + a2 + a3;
        float q = a0 * a0 + a1 * a1 + a2 * a2 + a3 * a3;
#pragma unroll
        for (int off = 16; off > 0; off >>= 1) {
            s += __shfl_down_sync(0xffffffffu, s, off);
            q += __shfl_down_sync(0xffffffffu, q, off);
        }
        if ((tid & 31) == 0) {
            atomicAdd(&stats[oc], (double)s);
            atomicAdd(&stats[16 + oc], (double)q);
        }
    }
}

// ---------------- conv_s2_v5: stride-2, FFMA2, OCPT=16, pre-transposed weights ------
// Input smem duplicated (v,v) u64; weights pre-transposed oc-major in gmem (wT) so
// the weight loader is a straight float4 copy. One warp = 16 ocs over the full tile.
template <int CIN, int COUTB, int OCPT, int TZ, int TY, int TXV, int ICC>
__global__ void __launch_bounds__(32*(COUTB/OCPT)) conv_s2_v5(
    const float* __restrict__ in, const float* __restrict__ wT,
    const float* __restrict__ bias,
    const float* __restrict__ tsc, const float* __restrict__ tsh,
    float* __restrict__ out, double* __restrict__ stats,
    int Din, int Dout, int ntx, int nty, int coutTot) {
    constexpr int VT = TZ * TY * TXV;
    constexpr int GROUPS = COUTB / OCPT;
    constexpr int THREADS = VT * GROUPS / (32 / 32) == 0 ? 0 : 32 * GROUPS;  // = 32*GROUPS
    constexpr int NPAIR = OCPT / 2;
    constexpr int IZ = 2 * TZ + 1;
    constexpr int IYE = 2 * TY + 1;
    constexpr int IX = 8 * TXV + 1;
    constexpr int IXP2 = 8 * TXV + 2;   // u64/row, even
    constexpr int NIN = ICC * IZ * IYE * IXP2;
    constexpr int NW  = COUTB * ICC * 27;
    static_assert(VT == 32, "warp == one oc-group over the full tile");
    static_assert(NPAIR == 8, "tuned for OCPT=16");
    static_assert((IXP2 & 1) == 0, "row stride must be even u64s");

    extern __shared__ float sm[];
    u64t*  sInD = reinterpret_cast<u64t*>(sm);  // NIN u64
    float* sW   = sm + 2 * NIN;                  // NW floats, oc-major
    __shared__ float bsum[COUTB], bsq[COUTB];

    int tid = threadIdx.x;
    int b = blockIdx.y;
    int ocBase = blockIdx.z * COUTB;
    int t = blockIdx.x;
    int tx = t % ntx, ty = (t / ntx) % nty, tz = t / (ntx * nty);

    int vt = tid & 31;
    int group = tid >> 5;
    int oxv = vt % TXV;
    int oy  = (vt / TXV) % TY;
    int oz  = vt / (TXV * TY);

    u64t acc[NPAIR][4];
#pragma unroll
    for (int p = 0; p < NPAIR; p++)
#pragma unroll
        for (int u = 0; u < 4; u++) acc[p][u] = 0ULL;

    int ginz = tz * (2 * TZ) - 1;
    int giny = ty * (2 * TY) - 1;
    int ginx = tx * (8 * TXV) - 1;

    for (int c0 = 0; c0 < CIN; c0 += ICC) {
        __syncthreads();
        // input load (BN+relu folded), store duplicated (v,v)
        for (int i = tid; i < NIN; i += THREADS) {
            int ix = i % IXP2;
            int r  = i / IXP2;
            int iy = r % IYE;
            int r2 = r / IYE;
            int iz = r2 % IZ;
            int ic = r2 / IZ;
            int gz = ginz + iz, gy = giny + iy, gx = ginx + ix;
            float v = 0.f;
            if (ix < IX && (unsigned)gz < (unsigned)Din &&
                (unsigned)gy < (unsigned)Din && (unsigned)gx < (unsigned)Din) {
                v = in[(((b * CIN + c0 + ic) * Din + gz) * Din + gy) * Din + gx];
                v = fmaxf(fmaf(v, tsc[c0 + ic], tsh[c0 + ic]), 0.f);
            }
            sInD[i] = pack2f(v, v);
        }
        // weight load: straight vector copy (wT already oc-major; oc-range offset)
        {
            const float* src = wT + (c0 * 27 + 0) * coutTot;  // rows [c0*27, (c0+ICC)*27)
            if (COUTB == coutTot) {
                for (int i = tid * 4; i < NW; i += THREADS * 4)
                    *reinterpret_cast<float4*>(&sW[i]) =
                        *reinterpret_cast<const float4*>(&src[i]);
            } else {
                for (int i = tid * 4; i < NW; i += THREADS * 4) {
                    int ocl = i % COUTB;
                    int row = i / COUTB;
                    *reinterpret_cast<float4*>(&sW[i]) =
                        *reinterpret_cast<const float4*>(&src[row * coutTot + ocBase + ocl]);
                }
            }
        }
        __syncthreads();

#pragma unroll
        for (int ic = 0; ic < ICC; ic++) {
#pragma unroll
            for (int kd = 0; kd < 3; kd++)
#pragma unroll
                for (int kh = 0; kh < 3; kh++) {
                    const u64t* ip =
                        &sInD[((ic * IZ + (2 * oz + kd)) * IYE + (2 * oy + kh)) * IXP2 +
                              8 * oxv];
                    ulonglong2 q0 = *reinterpret_cast<const ulonglong2*>(ip);
                    ulonglong2 q1 = *reinterpret_cast<const ulonglong2*>(ip + 2);
                    ulonglong2 q2 = *reinterpret_cast<const ulonglong2*>(ip + 4);
                    ulonglong2 q3 = *reinterpret_cast<const ulonglong2*>(ip + 6);
                    u64t iv8 = ip[8];
                    u64t ivd[9] = {q0.x, q0.y, q1.x, q1.y, q2.x, q2.y, q3.x, q3.y, iv8};
                    int k9 = kd * 3 + kh;
                    const float* wb_ = &sW[((ic * 9 + k9) * 3) * COUTB + group * OCPT];
#pragma unroll
                    for (int kw = 0; kw < 3; kw++) {
                        const ulonglong2* wp =
                            reinterpret_cast<const ulonglong2*>(wb_ + kw * COUTB);
                        ulonglong2 wq0 = wp[0];
                        ulonglong2 wq1 = wp[1];
                        ulonglong2 wq2 = wp[2];
                        ulonglong2 wq3 = wp[3];
#pragma unroll
                        for (int u = 0; u < 4; u++) {
                            u64t iv = ivd[2 * u + kw];
                            ffma2(acc[0][u], wq0.x, iv);
                            ffma2(acc[1][u], wq0.y, iv);
                            ffma2(acc[2][u], wq1.x, iv);
                            ffma2(acc[3][u], wq1.y, iv);
                            ffma2(acc[4][u], wq2.x, iv);
                            ffma2(acc[5][u], wq2.y, iv);
                            ffma2(acc[6][u], wq3.x, iv);
                            ffma2(acc[7][u], wq3.y, iv);
                        }
                    }
                }
        }
    }

    int gz = tz * TZ + oz, gy = ty * TY + oy;
    int gx = tx * (4 * TXV) + oxv * 4;
#pragma unroll 1
    for (int p = 0; p < NPAIR; p++) {
        float o0[4], o1[4];
#pragma unroll
        for (int u = 0; u < 4; u++) unpack2f(acc[p][u], o0[u], o1[u]);
#pragma unroll
        for (int h = 0; h < 2; h++) {
            float* ov = h ? o1 : o0;
            int ocl = group * OCPT + 2 * p + h;
            int oc = ocBase + ocl;
            float bb = bias[oc];
            float a0 = ov[0] + bb, a1 = ov[1] + bb, a2 = ov[2] + bb, a3 = ov[3] + bb;
            *reinterpret_cast<float4*>(
                &out[(((b * coutTot + oc) * Dout + gz) * Dout + gy) * Dout + gx]) =
                make_float4(a0, a1, a2, a3);

            float s = a0 + a1 + a2 + a3;
            float q = a0 * a0 + a1 * a1 + a2 * a2 + a3 * a3;
#pragma unroll
            for (int off = 16; off > 0; off >>= 1) {
                s += __shfl_down_sync(0xffffffffu, s, off);
                q += __shfl_down_sync(0xffffffffu, q, off);
            }
            if (vt == 0) { bsum[ocl] = s; bsq[ocl] = q; }
        }
    }
    __syncthreads();
    if (tid < COUTB) {
        atomicAdd(&stats[ocBase + tid], (double)bsum[tid]);
        atomicAdd(&stats[coutTot + ocBase + tid], (double)bsq[tid]);
    }
}

// ---------------- old generic stride-2 conv (kept for tiny stage 4) ----------------
template <int CIN, int COUTB, int OCPT>
__global__ void __launch_bounds__(128) conv_s2_kernel(
    const float* __restrict__ in, const float* __restrict__ w,
    const float* __restrict__ bias,
    const float* __restrict__ tsc, const float* __restrict__ tsh,
    float* __restrict__ out, double* __restrict__ stats,
    int Din, int Dout, int ntile, int coutTot) {
    constexpr int ICC = 16;
    constexpr int NIN = ICC * 729;
    constexpr int NW  = COUTB * ICC * 27;
    extern __shared__ float sm[];
    float* sIn = sm;
    float* sW  = sm + NIN;
    __shared__ float bsum[COUTB], bsq[COUTB];

    int tid = threadIdx.x;
    int b = blockIdx.y;
    int ocBase = blockIdx.z * COUTB;
    int t = blockIdx.x;
    int tz = t / (ntile * ntile), ty = (t / ntile) % ntile, tx = t % ntile;
    int pair = tid & 31, group = tid >> 5;
    int oz = pair >> 3, oy = (pair >> 1) & 3, px = pair & 1;

    if (tid < COUTB) { bsum[tid] = 0.f; bsq[tid] = 0.f; }

    float acc0[OCPT], acc1[OCPT];
#pragma unroll
    for (int j = 0; j < OCPT; j++) { acc0[j] = 0.f; acc1[j] = 0.f; }

    for (int c0 = 0; c0 < CIN; c0 += ICC) {
        __syncthreads();
        for (int i = tid; i < NIN; i += 128) {
            int ic = i / 729, r = i % 729;
            int iz = r / 81, iy = (r / 9) % 9, ix = r % 9;
            int gz = tz * 8 - 1 + iz, gy = ty * 8 - 1 + iy, gx = tx * 8 - 1 + ix;
            float v = 0.f;
            if ((unsigned)gz < (unsigned)Din && (unsigned)gy < (unsigned)Din &&
                (unsigned)gx < (unsigned)Din) {
                v = in[(((b * CIN + c0 + ic) * Din + gz) * Din + gy) * Din + gx];
                v = fmaxf(fmaf(v, tsc[c0 + ic], tsh[c0 + ic]), 0.f);
            }
            sIn[i] = v;
        }
        for (int i = tid; i < NW; i += 128) {
            int ocl = i / (ICC * 27), r = i % (ICC * 27);
            sW[i] = w[((ocBase + ocl) * CIN + c0) * 27 + r];
        }
        __syncthreads();

#pragma unroll 1
        for (int ic = 0; ic < ICC; ic++) {
            const float* wrow = &sW[(group * OCPT) * ICC * 27 + ic * 27];
#pragma unroll
            for (int kd = 0; kd < 3; kd++)
#pragma unroll
                for (int kh = 0; kh < 3; kh++) {
                    int base = ((ic * 9 + (2 * oz + kd)) * 9 + (2 * oy + kh)) * 9 + 4 * px;
                    float ivs[5];
#pragma unroll
                    for (int u = 0; u < 5; u++) ivs[u] = sIn[base + u];
#pragma unroll
                    for (int kw = 0; kw < 3; kw++) {
#pragma unroll
                        for (int j = 0; j < OCPT; j++) {
                            float wv = wrow[j * ICC * 27 + (kd * 3 + kh) * 3 + kw];
                            acc0[j] = fmaf(ivs[kw], wv, acc0[j]);
                            acc1[j] = fmaf(ivs[kw + 2], wv, acc1[j]);
                        }
                    }
                }
        }
    }

    int gz = tz * 4 + oz, gy = ty * 4 + oy, gx = tx * 4 + 2 * px;
#pragma unroll
    for (int j = 0; j < OCPT; j++) {
        int oc = ocBase + group * OCPT + j;
        float bb = bias[oc];
        float o0 = acc0[j] + bb, o1 = acc1[j] + bb;
        *reinterpret_cast<float2*>(
            &out[(((b * coutTot + oc) * Dout + gz) * Dout + gy) * Dout + gx]) =
            make_float2(o0, o1);

        float s = o0 + o1, q = o0 * o0 + o1 * o1;
#pragma unroll
        for (int off = 16; off > 0; off >>= 1) {
            s += __shfl_down_sync(0xffffffffu, s, off);
            q += __shfl_down_sync(0xffffffffu, q, off);
        }
        if (pair == 0) {
            atomicAdd(&bsum[group * OCPT + j], s);
            atomicAdd(&bsq[group * OCPT + j], q);
        }
    }
    __syncthreads();
    if (tid < COUTB) {
        atomicAdd(&stats[ocBase + tid], (double)bsum[tid]);
        atomicAdd(&stats[coutTot + ocBase + tid], (double)bsq[tid]);
    }
}

// ---------------- heads: 12 dot products + affine matrix composition ----------------
__device__ __forceinline__ void ident4(float* M) {
#pragma unroll
    for (int i = 0; i < 16; i++) M[i] = (i % 5 == 0) ? 1.f : 0.f;
}
__device__ __forceinline__ void mm4(const float* A, const float* B, float* C) {
#pragma unroll
    for (int i = 0; i < 4; i++)
#pragma unroll
        for (int j = 0; j < 4; j++)
            C[i * 4 + j] = A[i * 4 + 0] * B[0 + j] + A[i * 4 + 1] * B[4 + j] +
                           A[i * 4 + 2] * B[8 + j] + A[i * 4 + 3] * B[12 + j];
}

__global__ void __launch_bounds__(256) heads_kernel(
    const float* __restrict__ xs, const float* __restrict__ sc, const float* __restrict__ sh,
    const float* __restrict__ tw, const float* __restrict__ tb,
    const float* __restrict__ rw, const float* __restrict__ rb,
    const float* __restrict__ sw_, const float* __restrict__ sb_,
    const float* __restrict__ shw, const float* __restrict__ shb,
    float* __restrict__ theta) {
    __shared__ float red[12 * 256];
    int b = blockIdx.x, tid = threadIdx.x;
    float p[12];
#pragma unroll
    for (int r = 0; r < 12; r++) p[r] = 0.f;
    for (int i = tid; i < 4096; i += 256) {
        int c = i >> 6;
        float v = fmaxf(fmaf(xs[b * 4096 + i], sc[c], sh[c]), 0.f);
#pragma unroll
        for (int r = 0; r < 3; r++) {
            p[r]     = fmaf(v, tw[r * 4096 + i], p[r]);
            p[3 + r] = fmaf(v, rw[r * 4096 + i], p[3 + r]);
            p[6 + r] = fmaf(v, sw_[r * 4096 + i], p[6 + r]);
            p[9 + r] = fmaf(v, shw[r * 4096 + i], p[9 + r]);
        }
    }
#pragma unroll
    for (int r = 0; r < 12; r++) red[r * 256 + tid] = p[r];
    __syncthreads();
    for (int s = 128; s > 0; s >>= 1) {
        if (tid < s)
#pragma unroll
            for (int r = 0; r < 12; r++) red[r * 256 + tid] += red[r * 256 + tid + s];
        __syncthreads();
    }
    if (tid == 0) {
        const float PI4 = 0.7853981633974483f;
        float tr[3], ro[3], scp[3], shp[3];
#pragma unroll
        for (int r = 0; r < 3; r++) {
            tr[r]  = tanhf(red[r * 256] + tb[r]) * 0.1f;
            ro[r]  = tanhf(red[(3 + r) * 256] + rb[r]) * PI4;
            scp[r] = tanhf(red[(6 + r) * 256] + sb_[r]) * 0.2f;
            shp[r] = tanhf(red[(9 + r) * 256] + shb[r]) * PI4;
        }
        float c0 = cosf(ro[0]), s0 = sinf(ro[0]);
        float c1 = cosf(ro[1]), s1 = sinf(ro[1]);
        float c2 = cosf(ro[2]), s2 = sinf(ro[2]);
        float cs0 = cosf(shp[0]), ss0 = sinf(shp[0]);
        float cs1 = cosf(shp[1]), ss1 = sinf(shp[1]);
        float cs2 = cosf(shp[2]), ss2 = sinf(shp[2]);

        float T[16], R1[16], R2[16], R3[16], S[16], H1[16], H2[16], H3[16];
        float R[16], Sh[16], ShT[16], A[16], B[16];
        ident4(T);  T[3] = tr[0]; T[7] = tr[1]; T[11] = tr[2];
        ident4(R1); R1[0] = c0; R1[1] = -s0; R1[4] = s0; R1[5] = c0;
        ident4(R2); R2[5] = c1; R2[6] = -s1; R2[9] = s1; R2[10] = c1;
        ident4(R3); R3[0] = c2; R3[1] = -s2; R3[4] = s2; R3[5] = c2;
        ident4(S);  S[0] = expf(scp[0]); S[5] = expf(scp[1]); S[10] = expf(scp[2]);
        ident4(H1); H1[5] = cs0; H1[6] = -ss0; H1[9] = ss0; H1[10] = cs0;
        ident4(H2); H2[0] = cs1; H2[2] = ss1; H2[8] = -ss1; H2[10] = cs1;
        ident4(H3); H3[0] = cs2; H3[1] = -ss2; H3[4] = ss2; H3[5] = cs2;

        mm4(R1, R2, A); mm4(A, R3, R);
        mm4(H1, H2, A); mm4(A, H3, Sh);
#pragma unroll
        for (int i = 0; i < 4; i++)
#pragma unroll
            for (int j = 0; j < 4; j++) ShT[i * 4 + j] = Sh[j * 4 + i];
        mm4(Sh, S, A); mm4(A, ShT, B); mm4(B, R, A); mm4(A, T, B);
#pragma unroll
        for (int i = 0; i < 12; i++) theta[b * 12 + i] = B[i];
    }
}

// ---------------- trilinear grid sample (zero padding, clamped gather) ----------------
__global__ void __launch_bounds__(256) sampler_kernel(
    const float* __restrict__ x, const float* __restrict__ theta,
    float* __restrict__ out) {
    int idx = blockIdx.x * 256 + threadIdx.x;
    int b = idx >> 18;
    int r = idx & 262143;
    int z = r >> 12, y = (r >> 6) & 63, xq = r & 63;
    const float st = 2.f / 63.f;
    float xx = fmaf((float)xq, st, -1.f);
    float yy = fmaf((float)y, st, -1.f);
    float zz = fmaf((float)z, st, -1.f);
    const float* th = &theta[b * 12];
    float g0 = th[0] * xx + th[1] * yy + th[2] * zz + th[3];
    float g1 = th[4] * xx + th[5] * yy + th[6] * zz + th[7];
    float g2 = th[8] * xx + th[9] * yy + th[10] * zz + th[11];
    float fx = ((g0 + 1.f) * 64.f - 1.f) * 0.5f;
    float fy = ((g1 + 1.f) * 64.f - 1.f) * 0.5f;
    float fz = ((g2 + 1.f) * 64.f - 1.f) * 0.5f;
    float x0f = floorf(fx), y0f = floorf(fy), z0f = floorf(fz);
    int x0 = (int)x0f, y0 = (int)y0f, z0 = (int)z0f;
    float wx1 = fx - x0f, wx0 = 1.f - wx1;
    float wy1 = fy - y0f, wy0 = 1.f - wy1;
    float wz1 = fz - z0f, wz0 = 1.f - wz1;
    const float* xb = &x[b << 18];
    float acc = 0.f;
#pragma unroll
    for (int dz = 0; dz < 2; dz++) {
        int zc = z0 + dz;
        float wz = dz ? wz1 : wz0;
        bool vz = (zc >= 0 && zc < 64);
        int zi = min(max(zc, 0), 63);
#pragma unroll
        for (int dy = 0; dy < 2; dy++) {
            int yc = y0 + dy;
            float wy = dy ? wy1 : wy0;
            bool vy = vz && (yc >= 0 && yc < 64);
            int yi = min(max(yc, 0), 63);
#pragma unroll
            for (int dx = 0; dx < 2; dx++) {
                int xc = x0 + dx;
                float wgt = wz * wy * (dx ? wx1 : wx0);
                bool v = vy && (xc >= 0 && xc < 64);
                int xi = min(max(xc, 0), 63);
                float val = xb[(zi * 64 + yi) * 64 + xi];
                acc += v ? val * wgt : 0.f;
            }
        }
    }
    out[idx] = acc;
}

// ---------------- launch ----------------
extern "C" void kernel_launch(void* const* d_in, const int* in_sizes, int n_in,
                              void* d_out, int out_size) {
    const float* x    = (const float*)d_in[0];
    const float* w00  = (const float*)d_in[1];
    const float* b00  = (const float*)d_in[2];
    const float* g00  = (const float*)d_in[3];
    const float* be00 = (const float*)d_in[4];
    const float* w0   = (const float*)d_in[5];
    const float* b0   = (const float*)d_in[6];
    const float* g0   = (const float*)d_in[7];
    const float* be0  = (const float*)d_in[8];
    const float* w1   = (const float*)d_in[9];
    const float* b1   = (const float*)d_in[10];
    const float* g1   = (const float*)d_in[11];
    const float* be1  = (const float*)d_in[12];
    const float* w2   = (const float*)d_in[13];
    const float* b2   = (const float*)d_in[14];
    const float* g2   = (const float*)d_in[15];
    const float* be2  = (const float*)d_in[16];
    const float* w3   = (const float*)d_in[17];
    const float* b3   = (const float*)d_in[18];
    const float* g3   = (const float*)d_in[19];
    const float* be3  = (const float*)d_in[20];
    const float* tw   = (const float*)d_in[21];
    const float* tb   = (const float*)d_in[22];
    const float* rw   = (const float*)d_in[23];
    const float* rb   = (const float*)d_in[24];
    const float* sw   = (const float*)d_in[25];
    const float* sb   = (const float*)d_in[26];
    const float* shw  = (const float*)d_in[27];
    const float* shb  = (const float*)d_in[28];

    float *buf0, *buf1, *buf2, *buf3, *buf4, *scale, *shift, *theta;
    float *wT0, *wT1, *wT2;
    double* stats;
    cudaGetSymbolAddress((void**)&buf0, g_buf0);
    cudaGetSymbolAddress((void**)&buf1, g_buf1);
    cudaGetSymbolAddress((void**)&buf2, g_buf2);
    cudaGetSymbolAddress((void**)&buf3, g_buf3);
    cudaGetSymbolAddress((void**)&buf4, g_buf4);
    cudaGetSymbolAddress((void**)&stats, g_stats);
    cudaGetSymbolAddress((void**)&scale, g_scale);
    cudaGetSymbolAddress((void**)&shift, g_shift);
    cudaGetSymbolAddress((void**)&theta, g_theta);
    cudaGetSymbolAddress((void**)&wT0, g_wT0);
    cudaGetSymbolAddress((void**)&wT1, g_wT1);
    cudaGetSymbolAddress((void**)&wT2, g_wT2);

    // smem: input 2*9*9*18*8 = 23328 B; weights COUTB*2*27*4
    const int SM_V5_S1  = 2 * 9 * 9 * 18 * 8 + 32 * 2 * 27 * 4;  // 30240
    const int SM_V5_S23 = 2 * 9 * 9 * 18 * 8 + 64 * 2 * 27 * 4;  // 37152
    const int SM_L3OLD = (16 * 729 + 16 * 16 * 27) * 4;          // 74304 (stage 4)
    cudaFuncSetAttribute(conv_s2_v5<16, 32, 16, 4, 4, 2, 2>,
                         cudaFuncAttributeMaxDynamicSharedMemorySize, SM_V5_S1);
    cudaFuncSetAttribute(conv_s2_v5<32, 64, 16, 4, 4, 2, 2>,
                         cudaFuncAttributeMaxDynamicSharedMemorySize, SM_V5_S23);
    cudaFuncSetAttribute(conv_s2_v5<64, 64, 16, 4, 4, 2, 2>,
                         cudaFuncAttributeMaxDynamicSharedMemorySize, SM_V5_S23);
    cudaFuncSetAttribute(conv_s2_kernel<64, 16, 4>,
                         cudaFuncAttributeMaxDynamicSharedMemorySize, SM_L3OLD);

    zero_stats_kernel<<<1, 512>>>(stats);

    // one-shot weight transposes (deterministic; cheap)
    transpose_w_kernel<<<(32 * 16 * 27 + 255) / 256, 256>>>(w0, wT0, 16 * 27, 32);
    transpose_w_kernel<<<(64 * 32 * 27 + 255) / 256, 256>>>(w1, wT1, 32 * 27, 64);
    transpose_w_kernel<<<(64 * 64 * 27 + 255) / 256, 256>>>(w2, wT2, 64 * 27, 64);

    // stage 0: conv00 1->16, 64^3 (FFMA2)
    conv00_v2<<<dim3(512, 16), 128>>>(x, w00, b00, buf0, stats + 0);
    finalize_kernel<<<1, 64>>>(stats + 0, g00, be00, scale + 0, shift + 0, 16,
                               1.0 / 4194304.0);

    // stage 1: 16->32, 64^3 -> 32^3; tile (4,4,8): 256 tiles; 64-thread blocks
    conv_s2_v5<16, 32, 16, 4, 4, 2, 2><<<dim3(256, 16, 1), 64, SM_V5_S1>>>(
        buf0, wT0, b0, scale + 0, shift + 0, buf1, stats + 32, 64, 32, 4, 8, 32);
    finalize_kernel<<<1, 64>>>(stats + 32, g0, be0, scale + 64, shift + 64, 32,
                               1.0 / 524288.0);

    // stage 2: 32->64, 32^3 -> 16^3; 32 tiles, full 64 oc per block
    conv_s2_v5<32, 64, 16, 4, 4, 2, 2><<<dim3(32, 16, 1), 128, SM_V5_S23>>>(
        buf1, wT1, b1, scale + 64, shift + 64, buf2, stats + 96, 32, 16, 2, 4, 64);
    finalize_kernel<<<1, 64>>>(stats + 96, g1, be1, scale + 128, shift + 128, 64,
                               1.0 / 65536.0);

    // stage 3: 64->64, 16^3 -> 8^3; 4 tiles, full 64 oc per block
    conv_s2_v5<64, 64, 16, 4, 4, 2, 2><<<dim3(4, 16, 1), 128, SM_V5_S23>>>(
        buf2, wT2, b2, scale + 128, shift + 128, buf3, stats + 224, 16, 8, 1, 2, 64);
    finalize_kernel<<<1, 64>>>(stats + 224, g2, be2, scale + 192, shift + 192, 64,
                               1.0 / 8192.0);

    // stage 4: 64->64, 8^3 -> 4^3 (tiny; old kernel, oc split into 4 z-blocks)
    conv_s2_kernel<64, 16, 4><<<dim3(1, 16, 4), 128, SM_L3OLD>>>(
        buf3, w3, b3, scale + 192, shift + 192, buf4, stats + 352, 8, 4, 1, 64);
    finalize_kernel<<<1, 64>>>(stats + 352, g3, be3, scale + 256, shift + 256, 64,
                               1.0 / 1024.0);

    // heads + affine composition
    heads_kernel<<<16, 256>>>(buf4, scale + 256, shift + 256, tw, tb, rw, rb, sw, sb,
                              shw, shb, theta);

    // grid sample
    sampler_kernel<<<16384, 256>>>(x, theta, (float*)d_out);
}

// round 8
// speedup vs baseline: 1.4491x; 1.4491x over previous
#include <cuda_runtime.h>
#include <math.h>

// ---------------- packed f32x2 helpers (sm_103a FFMA2 path) ----------------
typedef unsigned long long u64t;
__device__ __forceinline__ u64t pack2f(float lo, float hi) {
    u64t r;
    asm("mov.b64 %0, {%1, %2};" : "=l"(r)
        : "r"(__float_as_uint(lo)), "r"(__float_as_uint(hi)));
    return r;
}
__device__ __forceinline__ void ffma2(u64t& d, u64t a, u64t b) {
    asm("fma.rn.f32x2 %0, %1, %2, %0;" : "+l"(d) : "l"(a), "l"(b));
}
__device__ __forceinline__ void unpack2f(u64t v, float& lo, float& hi) {
    unsigned ulo, uhi;
    asm("mov.b64 {%0, %1}, %2;" : "=r"(ulo), "=r"(uhi) : "l"(v));
    lo = __uint_as_float(ulo);
    hi = __uint_as_float(uhi);
}

// ---------------- persistent device scratch (no allocations allowed) ----------------
__device__ float  g_buf0[16u*16u*64u*64u*64u];
__device__ float  g_buf1[16u*32u*32u*32u*32u];
__device__ float  g_buf2[16u*64u*16u*16u*16u];
__device__ float  g_buf3[16u*64u*8u*8u*8u];
__device__ float  g_buf4[16u*64u*4u*4u*4u];
__device__ double g_stats[480];
__device__ float  g_scale[5*64];
__device__ float  g_shift[5*64];
__device__ float  g_theta[16*12];
__device__ float  g_wT0[32*16*27];
__device__ float  g_wT1[64*32*27];
__device__ float  g_wT2[64*64*27];

// ---------------- utility kernels ----------------
__global__ void zero_stats_kernel(double* s) {
    int i = threadIdx.x;
    if (i < 480) s[i] = 0.0;
}

__global__ void finalize_kernel(const double* __restrict__ stats,
                                const float* __restrict__ g, const float* __restrict__ be,
                                float* __restrict__ sc, float* __restrict__ sh,
                                int C, double invN) {
    int c = threadIdx.x;
    if (c < C) {
        double mean = stats[c] * invN;
        double var  = stats[C + c] * invN - mean * mean;
        float a = g[c] * (float)(1.0 / sqrt(var + 1e-5));
        sc[c] = a;
        sh[c] = be[c] - (float)mean * a;
    }
}

// weight transpose: w[oc][icr] -> wT[icr][oc]
__global__ void transpose_w_kernel(const float* __restrict__ w, float* __restrict__ wT,
                                   int cin27, int cout) {
    int i = blockIdx.x * 256 + threadIdx.x;
    if (i < cin27 * cout) {
        int oc = i % cout, icr = i / cout;
        wT[i] = w[oc * cin27 + icr];
    }
}

// ---------------- conv00 v2: 1->16 ch, stride 1, pad 1, 64^3, FFMA2 ----------------
__global__ void __launch_bounds__(128) conv00_v2(
    const float* __restrict__ x, const float* __restrict__ w,
    const float* __restrict__ bias, float* __restrict__ out,
    double* __restrict__ stats) {
    __shared__ float sIn[1000];
    __shared__ float sWd[864];

    int tid = threadIdx.x;
    int b = blockIdx.y;
    int t = blockIdx.x;
    int tz = t >> 6, ty = (t >> 3) & 7, tx = t & 7;

    for (int i = tid; i < 1000; i += 128) {
        int iz = i / 100, iy = (i / 10) % 10, ix = i % 10;
        int gz = tz * 8 - 1 + iz, gy = ty * 8 - 1 + iy, gx = tx * 8 - 1 + ix;
        float v = 0.f;
        if ((unsigned)gz < 64u && (unsigned)gy < 64u && (unsigned)gx < 64u)
            v = x[((b * 64 + gz) * 64 + gy) * 64 + gx];
        sIn[i] = v;
    }
    for (int i = tid; i < 432; i += 128) {
        int k = i >> 4, oc = i & 15;
        float wv = w[oc * 27 + k];
        sWd[k * 32 + oc * 2]     = wv;
        sWd[k * 32 + oc * 2 + 1] = wv;
    }
    __syncthreads();

    int sz = tid >> 4, sy = (tid >> 1) & 7, sx = tid & 1;

    u64t acc[16][2];
#pragma unroll
    for (int oc = 0; oc < 16; oc++) { acc[oc][0] = 0ULL; acc[oc][1] = 0ULL; }

#pragma unroll
    for (int kd = 0; kd < 3; kd++)
#pragma unroll
        for (int kh = 0; kh < 3; kh++) {
            int base = (sz + kd) * 100 + (sy + kh) * 10 + sx * 4;
            float i0 = sIn[base], i1 = sIn[base + 1], i2 = sIn[base + 2];
            float i3 = sIn[base + 3], i4 = sIn[base + 4], i5 = sIn[base + 5];
            u64t P[5];
            P[0] = pack2f(i0, i1); P[1] = pack2f(i1, i2); P[2] = pack2f(i2, i3);
            P[3] = pack2f(i3, i4); P[4] = pack2f(i4, i5);
            int k9 = kd * 3 + kh;
#pragma unroll
            for (int kw = 0; kw < 3; kw++) {
                const u64t* wrow =
                    reinterpret_cast<const u64t*>(&sWd[(k9 * 3 + kw) * 32]);
#pragma unroll
                for (int oc = 0; oc < 16; oc++) {
                    u64t wp = wrow[oc];
                    ffma2(acc[oc][0], P[kw], wp);
                    ffma2(acc[oc][1], P[kw + 2], wp);
                }
            }
        }

    int gz = tz * 8 + sz, gy = ty * 8 + sy, gx = tx * 8 + sx * 4;
#pragma unroll 1
    for (int oc = 0; oc < 16; oc++) {
        float a0, a1, a2, a3;
        unpack2f(acc[oc][0], a0, a1);
        unpack2f(acc[oc][1], a2, a3);
        float bb = bias[oc];
        a0 += bb; a1 += bb; a2 += bb; a3 += bb;
        *reinterpret_cast<float4*>(&out[(((b * 16 + oc) * 64 + gz) * 64 + gy) * 64 + gx]) =
            make_float4(a0, a1, a2, a3);

        float s = a0 + a1 + a2 + a3;
        float q = a0 * a0 + a1 * a1 + a2 * a2 + a3 * a3;
#pragma unroll
        for (int off = 16; off > 0; off >>= 1) {
            s += __shfl_down_sync(0xffffffffu, s, off);
            q += __shfl_down_sync(0xffffffffu, q, off);
        }
        if ((tid & 31) == 0) {
            atomicAdd(&stats[oc], (double)s);
            atomicAdd(&stats[16 + oc], (double)q);
        }
    }
}

// ---------------- conv_s2_v6: stride-2, FFMA2, slot-offset loader -------------------
// Tile fixed 4x4x8 outputs (VT=32, warp == one oc-group). Per-slot gmem offsets and
// channel ids are computed ONCE per block and packed into one register each:
//   goff = (offset within batch-image block) | (local channel << 24);  invalid = -1.
// Per c0 the loader is: predicated LDG + BN (smem tables) + dup STS.  Weights come
// from pre-transposed wT (oc-major) via straight float4 copy (COUTB == coutTot).
template <int CIN, int COUTB, int OCPT, int ICC, int MAXB>
__global__ void __launch_bounds__(128, MAXB) conv_s2_v6(
    const float* __restrict__ in, const float* __restrict__ wT,
    const float* __restrict__ bias,
    const float* __restrict__ tsc, const float* __restrict__ tsh,
    float* __restrict__ out, double* __restrict__ stats,
    int Din, int Dout, int ntx, int nty, int coutTot) {
    constexpr int GROUPS = COUTB / OCPT;
    constexpr int THREADS = 32 * GROUPS;
    constexpr int NPAIR = OCPT / 2;
    constexpr int IZ = 9, IYE = 9, IX = 17, IXP2 = 18;  // tile 4x4x8 outputs
    constexpr int NINU = ICC * IZ * IYE * IXP2;         // u64 elements
    constexpr int NSLOT = (NINU + THREADS - 1) / THREADS;
    constexpr int NW = COUTB * ICC * 27;
    static_assert(THREADS == 128, "tile mapping assumes 128 threads");
    static_assert((NPAIR & 1) == 0, "NPAIR must be even");

    extern __shared__ float sm[];
    u64t*  sInD = reinterpret_cast<u64t*>(sm);            // NSLOT*THREADS u64 (padded)
    float* sW   = sm + 2 * NSLOT * THREADS;               // NW floats
    __shared__ float bsum[COUTB], bsq[COUTB];
    __shared__ float sScale[CIN], sShift[CIN];

    int tid = threadIdx.x;
    int b = blockIdx.y;
    int ocBase = blockIdx.z * COUTB;
    int t = blockIdx.x;
    int tx = t % ntx, ty = (t / ntx) % nty, tz = t / (ntx * nty);

    int vt = tid & 31;
    int group = tid >> 5;
    int oxv = vt & 1;            // TXV=2
    int oy  = (vt >> 1) & 3;     // TY=4
    int oz  = vt >> 3;           // TZ=4

    if (tid < CIN) { sScale[tid] = tsc[tid]; sShift[tid] = tsh[tid]; }

    int ginz = tz * 8 - 1;
    int giny = ty * 8 - 1;
    int ginx = tx * 16 - 1;

    const float* inB = in + (long long)b * CIN * Din * Din * Din;
    const int chanStride = Din * Din * Din;

    // per-slot packed offsets (computed once per block)
    int goff[NSLOT];
    {
        int i = tid;
#pragma unroll
        for (int s = 0; s < NSLOT; s++, i += THREADS) {
            int ix = i % IXP2;
            int r  = i / IXP2;
            int iy = r % IYE;
            int r2 = r / IYE;
            int iz = r2 % IZ;
            int icl = r2 / IZ;
            int gz = ginz + iz, gy = giny + iy, gx = ginx + ix;
            bool ok = (i < NINU) && (ix < IX) &&
                      ((unsigned)gz < (unsigned)Din) &&
                      ((unsigned)gy < (unsigned)Din) &&
                      ((unsigned)gx < (unsigned)Din);
            int off = ((icl * Din + gz) * Din + gy) * Din + gx;
            goff[s] = ok ? (off | (icl << 24)) : -1;
        }
    }

    u64t acc[NPAIR][4];
#pragma unroll
    for (int p = 0; p < NPAIR; p++)
#pragma unroll
        for (int u = 0; u < 4; u++) acc[p][u] = 0ULL;

#pragma unroll 1
    for (int c0 = 0; c0 < CIN; c0 += ICC) {
        __syncthreads();
        // input load: predicated LDG + BN + dup store
        const float* inC = inB + c0 * chanStride;
#pragma unroll
        for (int s = 0; s < NSLOT; s++) {
            int pk = goff[s];
            float v = 0.f;
            if (pk >= 0) {
                int off = pk & 0x00FFFFFF;
                int icl = pk >> 24;
                v = inC[off];
                v = fmaxf(fmaf(v, sScale[c0 + icl], sShift[c0 + icl]), 0.f);
            }
            sInD[s * THREADS + tid] = pack2f(v, v);
        }
        // weight load: straight float4 copy (wT oc-major, COUTB == coutTot)
        {
            const float* srcw = wT + c0 * 27 * COUTB;
#pragma unroll
            for (int i = tid * 4; i < NW; i += THREADS * 4)
                *reinterpret_cast<float4*>(&sW[i]) =
                    *reinterpret_cast<const float4*>(&srcw[i]);
        }
        __syncthreads();

#pragma unroll
        for (int ic = 0; ic < ICC; ic++) {
#pragma unroll
            for (int kd = 0; kd < 3; kd++)
#pragma unroll
                for (int kh = 0; kh < 3; kh++) {
                    const u64t* ip =
                        &sInD[((ic * IZ + (2 * oz + kd)) * IYE + (2 * oy + kh)) * IXP2 +
                              8 * oxv];
                    ulonglong2 q0 = *reinterpret_cast<const ulonglong2*>(ip);
                    ulonglong2 q1 = *reinterpret_cast<const ulonglong2*>(ip + 2);
                    ulonglong2 q2 = *reinterpret_cast<const ulonglong2*>(ip + 4);
                    ulonglong2 q3 = *reinterpret_cast<const ulonglong2*>(ip + 6);
                    u64t iv8 = ip[8];
                    u64t ivd[9] = {q0.x, q0.y, q1.x, q1.y, q2.x, q2.y, q3.x, q3.y, iv8};
                    int k9 = kd * 3 + kh;
                    const float* wb_ = &sW[(ic * 27 + k9 * 3) * COUTB + group * OCPT];
#pragma unroll
                    for (int kw = 0; kw < 3; kw++) {
                        ulonglong2 wq[NPAIR / 2];
#pragma unroll
                        for (int pp = 0; pp < NPAIR / 2; pp++)
                            wq[pp] = *reinterpret_cast<const ulonglong2*>(
                                wb_ + kw * COUTB + pp * 4);
#pragma unroll
                        for (int u = 0; u < 4; u++) {
                            u64t iv = ivd[2 * u + kw];
#pragma unroll
                            for (int pp = 0; pp < NPAIR / 2; pp++) {
                                ffma2(acc[2 * pp][u], wq[pp].x, iv);
                                ffma2(acc[2 * pp + 1][u], wq[pp].y, iv);
                            }
                        }
                    }
                }
        }
    }

    int gz = tz * 4 + oz, gy = ty * 4 + oy;
    int gx = tx * 8 + oxv * 4;
#pragma unroll 1
    for (int p = 0; p < NPAIR; p++) {
        float o0[4], o1[4];
#pragma unroll
        for (int u = 0; u < 4; u++) unpack2f(acc[p][u], o0[u], o1[u]);
#pragma unroll
        for (int h = 0; h < 2; h++) {
            float* ov = h ? o1 : o0;
            int ocl = group * OCPT + 2 * p + h;
            int oc = ocBase + ocl;
            float bb = bias[oc];
            float a0 = ov[0] + bb, a1 = ov[1] + bb, a2 = ov[2] + bb, a3 = ov[3] + bb;
            *reinterpret_cast<float4*>(
                &out[(((b * coutTot + oc) * Dout + gz) * Dout + gy) * Dout + gx]) =
                make_float4(a0, a1, a2, a3);

            float s = a0 + a1 + a2 + a3;
            float q = a0 * a0 + a1 * a1 + a2 * a2 + a3 * a3;
#pragma unroll
            for (int off = 16; off > 0; off >>= 1) {
                s += __shfl_down_sync(0xffffffffu, s, off);
                q += __shfl_down_sync(0xffffffffu, q, off);
            }
            if (vt == 0) { bsum[ocl] = s; bsq[ocl] = q; }
        }
    }
    __syncthreads();
    if (tid < COUTB) {
        atomicAdd(&stats[ocBase + tid], (double)bsum[tid]);
        atomicAdd(&stats[coutTot + ocBase + tid], (double)bsq[tid]);
    }
}

// ---------------- old generic stride-2 conv (kept for tiny stage 4) ----------------
template <int CIN, int COUTB, int OCPT>
__global__ void __launch_bounds__(128) conv_s2_kernel(
    const float* __restrict__ in, const float* __restrict__ w,
    const float* __restrict__ bias,
    const float* __restrict__ tsc, const float* __restrict__ tsh,
    float* __restrict__ out, double* __restrict__ stats,
    int Din, int Dout, int ntile, int coutTot) {
    constexpr int ICC = 16;
    constexpr int NIN = ICC * 729;
    constexpr int NW  = COUTB * ICC * 27;
    extern __shared__ float sm[];
    float* sIn = sm;
    float* sW  = sm + NIN;
    __shared__ float bsum[COUTB], bsq[COUTB];

    int tid = threadIdx.x;
    int b = blockIdx.y;
    int ocBase = blockIdx.z * COUTB;
    int t = blockIdx.x;
    int tz = t / (ntile * ntile), ty = (t / ntile) % ntile, tx = t % ntile;
    int pair = tid & 31, group = tid >> 5;
    int oz = pair >> 3, oy = (pair >> 1) & 3, px = pair & 1;

    if (tid < COUTB) { bsum[tid] = 0.f; bsq[tid] = 0.f; }

    float acc0[OCPT], acc1[OCPT];
#pragma unroll
    for (int j = 0; j < OCPT; j++) { acc0[j] = 0.f; acc1[j] = 0.f; }

    for (int c0 = 0; c0 < CIN; c0 += ICC) {
        __syncthreads();
        for (int i = tid; i < NIN; i += 128) {
            int ic = i / 729, r = i % 729;
            int iz = r / 81, iy = (r / 9) % 9, ix = r % 9;
            int gz = tz * 8 - 1 + iz, gy = ty * 8 - 1 + iy, gx = tx * 8 - 1 + ix;
            float v = 0.f;
            if ((unsigned)gz < (unsigned)Din && (unsigned)gy < (unsigned)Din &&
                (unsigned)gx < (unsigned)Din) {
                v = in[(((b * CIN + c0 + ic) * Din + gz) * Din + gy) * Din + gx];
                v = fmaxf(fmaf(v, tsc[c0 + ic], tsh[c0 + ic]), 0.f);
            }
            sIn[i] = v;
        }
        for (int i = tid; i < NW; i += 128) {
            int ocl = i / (ICC * 27), r = i % (ICC * 27);
            sW[i] = w[((ocBase + ocl) * CIN + c0) * 27 + r];
        }
        __syncthreads();

#pragma unroll 1
        for (int ic = 0; ic < ICC; ic++) {
            const float* wrow = &sW[(group * OCPT) * ICC * 27 + ic * 27];
#pragma unroll
            for (int kd = 0; kd < 3; kd++)
#pragma unroll
                for (int kh = 0; kh < 3; kh++) {
                    int base = ((ic * 9 + (2 * oz + kd)) * 9 + (2 * oy + kh)) * 9 + 4 * px;
                    float ivs[5];
#pragma unroll
                    for (int u = 0; u < 5; u++) ivs[u] = sIn[base + u];
#pragma unroll
                    for (int kw = 0; kw < 3; kw++) {
#pragma unroll
                        for (int j = 0; j < OCPT; j++) {
                            float wv = wrow[j * ICC * 27 + (kd * 3 + kh) * 3 + kw];
                            acc0[j] = fmaf(ivs[kw], wv, acc0[j]);
                            acc1[j] = fmaf(ivs[kw + 2], wv, acc1[j]);
                        }
                    }
                }
        }
    }

    int gz = tz * 4 + oz, gy = ty * 4 + oy, gx = tx * 4 + 2 * px;
#pragma unroll
    for (int j = 0; j < OCPT; j++) {
        int oc = ocBase + group * OCPT + j;
        float bb = bias[oc];
        float o0 = acc0[j] + bb, o1 = acc1[j] + bb;
        *reinterpret_cast<float2*>(
            &out[(((b * coutTot + oc) * Dout + gz) * Dout + gy) * Dout + gx]) =
            make_float2(o0, o1);

        float s = o0 + o1, q = o0 * o0 + o1 * o1;
#pragma unroll
        for (int off = 16; off > 0; off >>= 1) {
            s += __shfl_down_sync(0xffffffffu, s, off);
            q += __shfl_down_sync(0xffffffffu, q, off);
        }
        if (pair == 0) {
            atomicAdd(&bsum[group * OCPT + j], s);
            atomicAdd(&bsq[group * OCPT + j], q);
        }
    }
    __syncthreads();
    if (tid < COUTB) {
        atomicAdd(&stats[ocBase + tid], (double)bsum[tid]);
        atomicAdd(&stats[coutTot + ocBase + tid], (double)bsq[tid]);
    }
}

// ---------------- heads: 12 dot products + affine matrix composition ----------------
__device__ __forceinline__ void ident4(float* M) {
#pragma unroll
    for (int i = 0; i < 16; i++) M[i] = (i % 5 == 0) ? 1.f : 0.f;
}
__device__ __forceinline__ void mm4(const float* A, const float* B, float* C) {
#pragma unroll
    for (int i = 0; i < 4; i++)
#pragma unroll
        for (int j = 0; j < 4; j++)
            C[i * 4 + j] = A[i * 4 + 0] * B[0 + j] + A[i * 4 + 1] * B[4 + j] +
                           A[i * 4 + 2] * B[8 + j] + A[i * 4 + 3] * B[12 + j];
}

__global__ void __launch_bounds__(256) heads_kernel(
    const float* __restrict__ xs, const float* __restrict__ sc, const float* __restrict__ sh,
    const float* __restrict__ tw, const float* __restrict__ tb,
    const float* __restrict__ rw, const float* __restrict__ rb,
    const float* __restrict__ sw_, const float* __restrict__ sb_,
    const float* __restrict__ shw, const float* __restrict__ shb,
    float* __restrict__ theta) {
    __shared__ float red[12 * 256];
    int b = blockIdx.x, tid = threadIdx.x;
    float p[12];
#pragma unroll
    for (int r = 0; r < 12; r++) p[r] = 0.f;
    for (int i = tid; i < 4096; i += 256) {
        int c = i >> 6;
        float v = fmaxf(fmaf(xs[b * 4096 + i], sc[c], sh[c]), 0.f);
#pragma unroll
        for (int r = 0; r < 3; r++) {
            p[r]     = fmaf(v, tw[r * 4096 + i], p[r]);
            p[3 + r] = fmaf(v, rw[r * 4096 + i], p[3 + r]);
            p[6 + r] = fmaf(v, sw_[r * 4096 + i], p[6 + r]);
            p[9 + r] = fmaf(v, shw[r * 4096 + i], p[9 + r]);
        }
    }
#pragma unroll
    for (int r = 0; r < 12; r++) red[r * 256 + tid] = p[r];
    __syncthreads();
    for (int s = 128; s > 0; s >>= 1) {
        if (tid < s)
#pragma unroll
            for (int r = 0; r < 12; r++) red[r * 256 + tid] += red[r * 256 + tid + s];
        __syncthreads();
    }
    if (tid == 0) {
        const float PI4 = 0.7853981633974483f;
        float tr[3], ro[3], scp[3], shp[3];
#pragma unroll
        for (int r = 0; r < 3; r++) {
            tr[r]  = tanhf(red[r * 256] + tb[r]) * 0.1f;
            ro[r]  = tanhf(red[(3 + r) * 256] + rb[r]) * PI4;
            scp[r] = tanhf(red[(6 + r) * 256] + sb_[r]) * 0.2f;
            shp[r] = tanhf(red[(9 + r) * 256] + shb[r]) * PI4;
        }
        float c0 = cosf(ro[0]), s0 = sinf(ro[0]);
        float c1 = cosf(ro[1]), s1 = sinf(ro[1]);
        float c2 = cosf(ro[2]), s2 = sinf(ro[2]);
        float cs0 = cosf(shp[0]), ss0 = sinf(shp[0]);
        float cs1 = cosf(shp[1]), ss1 = sinf(shp[1]);
        float cs2 = cosf(shp[2]), ss2 = sinf(shp[2]);

        float T[16], R1[16], R2[16], R3[16], S[16], H1[16], H2[16], H3[16];
        float R[16], Sh[16], ShT[16], A[16], B[16];
        ident4(T);  T[3] = tr[0]; T[7] = tr[1]; T[11] = tr[2];
        ident4(R1); R1[0] = c0; R1[1] = -s0; R1[4] = s0; R1[5] = c0;
        ident4(R2); R2[5] = c1; R2[6] = -s1; R2[9] = s1; R2[10] = c1;
        ident4(R3); R3[0] = c2; R3[1] = -s2; R3[4] = s2; R3[5] = c2;
        ident4(S);  S[0] = expf(scp[0]); S[5] = expf(scp[1]); S[10] = expf(scp[2]);
        ident4(H1); H1[5] = cs0; H1[6] = -ss0; H1[9] = ss0; H1[10] = cs0;
        ident4(H2); H2[0] = cs1; H2[2] = ss1; H2[8] = -ss1; H2[10] = cs1;
        ident4(H3); H3[0] = cs2; H3[1] = -ss2; H3[4] = ss2; H3[5] = cs2;

        mm4(R1, R2, A); mm4(A, R3, R);
        mm4(H1, H2, A); mm4(A, H3, Sh);
#pragma unroll
        for (int i = 0; i < 4; i++)
#pragma unroll
            for (int j = 0; j < 4; j++) ShT[i * 4 + j] = Sh[j * 4 + i];
        mm4(Sh, S, A); mm4(A, ShT, B); mm4(B, R, A); mm4(A, T, B);
#pragma unroll
        for (int i = 0; i < 12; i++) theta[b * 12 + i] = B[i];
    }
}

// ---------------- trilinear grid sample (zero padding, clamped gather) ----------------
__global__ void __launch_bounds__(256) sampler_kernel(
    const float* __restrict__ x, const float* __restrict__ theta,
    float* __restrict__ out) {
    int idx = blockIdx.x * 256 + threadIdx.x;
    int b = idx >> 18;
    int r = idx & 262143;
    int z = r >> 12, y = (r >> 6) & 63, xq = r & 63;
    const float st = 2.f / 63.f;
    float xx = fmaf((float)xq, st, -1.f);
    float yy = fmaf((float)y, st, -1.f);
    float zz = fmaf((float)z, st, -1.f);
    const float* th = &theta[b * 12];
    float g0 = th[0] * xx + th[1] * yy + th[2] * zz + th[3];
    float g1 = th[4] * xx + th[5] * yy + th[6] * zz + th[7];
    float g2 = th[8] * xx + th[9] * yy + th[10] * zz + th[11];
    float fx = ((g0 + 1.f) * 64.f - 1.f) * 0.5f;
    float fy = ((g1 + 1.f) * 64.f - 1.f) * 0.5f;
    float fz = ((g2 + 1.f) * 64.f - 1.f) * 0.5f;
    float x0f = floorf(fx), y0f = floorf(fy), z0f = floorf(fz);
    int x0 = (int)x0f, y0 = (int)y0f, z0 = (int)z0f;
    float wx1 = fx - x0f, wx0 = 1.f - wx1;
    float wy1 = fy - y0f, wy0 = 1.f - wy1;
    float wz1 = fz - z0f, wz0 = 1.f - wz1;
    const float* xb = &x[b << 18];
    float acc = 0.f;
#pragma unroll
    for (int dz = 0; dz < 2; dz++) {
        int zc = z0 + dz;
        float wz = dz ? wz1 : wz0;
        bool vz = (zc >= 0 && zc < 64);
        int zi = min(max(zc, 0), 63);
#pragma unroll
        for (int dy = 0; dy < 2; dy++) {
            int yc = y0 + dy;
            float wy = dy ? wy1 : wy0;
            bool vy = vz && (yc >= 0 && yc < 64);
            int yi = min(max(yc, 0), 63);
#pragma unroll
            for (int dx = 0; dx < 2; dx++) {
                int xc = x0 + dx;
                float wgt = wz * wy * (dx ? wx1 : wx0);
                bool v = vy && (xc >= 0 && xc < 64);
                int xi = min(max(xc, 0), 63);
                float val = xb[(zi * 64 + yi) * 64 + xi];
                acc += v ? val * wgt : 0.f;
            }
        }
    }
    out[idx] = acc;
}

// ---------------- launch ----------------
extern "C" void kernel_launch(void* const* d_in, const int* in_sizes, int n_in,
                              void* d_out, int out_size) {
    const float* x    = (const float*)d_in[0];
    const float* w00  = (const float*)d_in[1];
    const float* b00  = (const float*)d_in[2];
    const float* g00  = (const float*)d_in[3];
    const float* be00 = (const float*)d_in[4];
    const float* w0   = (const float*)d_in[5];
    const float* b0   = (const float*)d_in[6];
    const float* g0   = (const float*)d_in[7];
    const float* be0  = (const float*)d_in[8];
    const float* w1   = (const float*)d_in[9];
    const float* b1   = (const float*)d_in[10];
    const float* g1   = (const float*)d_in[11];
    const float* be1  = (const float*)d_in[12];
    const float* w2   = (const float*)d_in[13];
    const float* b2   = (const float*)d_in[14];
    const float* g2   = (const float*)d_in[15];
    const float* be2  = (const float*)d_in[16];
    const float* w3   = (const float*)d_in[17];
    const float* b3   = (const float*)d_in[18];
    const float* g3   = (const float*)d_in[19];
    const float* be3  = (const float*)d_in[20];
    const float* tw   = (const float*)d_in[21];
    const float* tb   = (const float*)d_in[22];
    const float* rw   = (const float*)d_in[23];
    const float* rb   = (const float*)d_in[24];
    const float* sw   = (const float*)d_in[25];
    const float* sb   = (const float*)d_in[26];
    const float* shw  = (const float*)d_in[27];
    const float* shb  = (const float*)d_in[28];

    float *buf0, *buf1, *buf2, *buf3, *buf4, *scale, *shift, *theta;
    float *wT0, *wT1, *wT2;
    double* stats;
    cudaGetSymbolAddress((void**)&buf0, g_buf0);
    cudaGetSymbolAddress((void**)&buf1, g_buf1);
    cudaGetSymbolAddress((void**)&buf2, g_buf2);
    cudaGetSymbolAddress((void**)&buf3, g_buf3);
    cudaGetSymbolAddress((void**)&buf4, g_buf4);
    cudaGetSymbolAddress((void**)&stats, g_stats);
    cudaGetSymbolAddress((void**)&scale, g_scale);
    cudaGetSymbolAddress((void**)&shift, g_shift);
    cudaGetSymbolAddress((void**)&theta, g_theta);
    cudaGetSymbolAddress((void**)&wT0, g_wT0);
    cudaGetSymbolAddress((void**)&wT1, g_wT1);
    cudaGetSymbolAddress((void**)&wT2, g_wT2);

    // NSLOT = ceil(2*9*9*18/128) = 23 -> input smem 23*128*8 = 23552 B
    const int SM_V6_S1  = 23 * 128 * 8 + 32 * 2 * 27 * 4;  // 30464
    const int SM_V6_S23 = 23 * 128 * 8 + 64 * 2 * 27 * 4;  // 37376
    const int SM_L3OLD  = (16 * 729 + 16 * 16 * 27) * 4;   // 74304 (stage 4)
    cudaFuncSetAttribute(conv_s2_v6<16, 32, 8, 2, 4>,
                         cudaFuncAttributeMaxDynamicSharedMemorySize, SM_V6_S1);
    cudaFuncSetAttribute(conv_s2_v6<32, 64, 16, 2, 3>,
                         cudaFuncAttributeMaxDynamicSharedMemorySize, SM_V6_S23);
    cudaFuncSetAttribute(conv_s2_v6<64, 64, 16, 2, 3>,
                         cudaFuncAttributeMaxDynamicSharedMemorySize, SM_V6_S23);
    cudaFuncSetAttribute(conv_s2_kernel<64, 16, 4>,
                         cudaFuncAttributeMaxDynamicSharedMemorySize, SM_L3OLD);

    zero_stats_kernel<<<1, 512>>>(stats);

    // one-shot weight transposes
    transpose_w_kernel<<<(32 * 16 * 27 + 255) / 256, 256>>>(w0, wT0, 16 * 27, 32);
    transpose_w_kernel<<<(64 * 32 * 27 + 255) / 256, 256>>>(w1, wT1, 32 * 27, 64);
    transpose_w_kernel<<<(64 * 64 * 27 + 255) / 256, 256>>>(w2, wT2, 64 * 27, 64);

    // stage 0: conv00 1->16, 64^3 (FFMA2)
    conv00_v2<<<dim3(512, 16), 128>>>(x, w00, b00, buf0, stats + 0);
    finalize_kernel<<<1, 64>>>(stats + 0, g00, be00, scale + 0, shift + 0, 16,
                               1.0 / 4194304.0);

    // stage 1: 16->32, 64^3 -> 32^3; 256 tiles (ntx=4, nty=8)
    conv_s2_v6<16, 32, 8, 2, 4><<<dim3(256, 16, 1), 128, SM_V6_S1>>>(
        buf0, wT0, b0, scale + 0, shift + 0, buf1, stats + 32, 64, 32, 4, 8, 32);
    finalize_kernel<<<1, 64>>>(stats + 32, g0, be0, scale + 64, shift + 64, 32,
                               1.0 / 524288.0);

    // stage 2: 32->64, 32^3 -> 16^3; 32 tiles (ntx=2, nty=4)
    conv_s2_v6<32, 64, 16, 2, 3><<<dim3(32, 16, 1), 128, SM_V6_S23>>>(
        buf1, wT1, b1, scale + 64, shift + 64, buf2, stats + 96, 32, 16, 2, 4, 64);
    finalize_kernel<<<1, 64>>>(stats + 96, g1, be1, scale + 128, shift + 128, 64,
                               1.0 / 65536.0);

    // stage 3: 64->64, 16^3 -> 8^3; 4 tiles (ntx=1, nty=2)
    conv_s2_v6<64, 64, 16, 2, 3><<<dim3(4, 16, 1), 128, SM_V6_S23>>>(
        buf2, wT2, b2, scale + 128, shift + 128, buf3, stats + 224, 16, 8, 1, 2, 64);
    finalize_kernel<<<1, 64>>>(stats + 224, g2, be2, scale + 192, shift + 192, 64,
                               1.0 / 8192.0);

    // stage 4: 64->64, 8^3 -> 4^3 (tiny; old kernel, oc split into 4 z-blocks)
    conv_s2_kernel<64, 16, 4><<<dim3(1, 16, 4), 128, SM_L3OLD>>>(
        buf3, w3, b3, scale + 192, shift + 192, buf4, stats + 352, 8, 4, 1, 64);
    finalize_kernel<<<1, 64>>>(stats + 352, g3, be3, scale + 256, shift + 256, 64,
                               1.0 / 1024.0);

    // heads + affine composition
    heads_kernel<<<16, 256>>>(buf4, scale + 256, shift + 256, tw, tb, rw, rb, sw, sb,
                              shw, shb, theta);

    // grid sample
    sampler_kernel<<<16384, 256>>>(x, theta, (float*)d_out);
}

// round 9
// speedup vs baseline: 1.4619x; 1.0088x over previous
#include <cuda_runtime.h>
#include <math.h>

// ---------------- packed f32x2 helpers (sm_103a FFMA2 path) ----------------
typedef unsigned long long u64t;
__device__ __forceinline__ u64t pack2f(float lo, float hi) {
    u64t r;
    asm("mov.b64 %0, {%1, %2};" : "=l"(r)
        : "r"(__float_as_uint(lo)), "r"(__float_as_uint(hi)));
    return r;
}
__device__ __forceinline__ void ffma2(u64t& d, u64t a, u64t b) {
    asm("fma.rn.f32x2 %0, %1, %2, %0;" : "+l"(d) : "l"(a), "l"(b));
}
__device__ __forceinline__ void unpack2f(u64t v, float& lo, float& hi) {
    unsigned ulo, uhi;
    asm("mov.b64 {%0, %1}, %2;" : "=r"(ulo), "=r"(uhi) : "l"(v));
    lo = __uint_as_float(ulo);
    hi = __uint_as_float(uhi);
}

// ---------------- persistent device scratch (no allocations allowed) ----------------
__device__ float  g_buf0[16u*16u*64u*64u*64u];
__device__ float  g_buf1[16u*32u*32u*32u*32u];
__device__ float  g_buf2[16u*64u*16u*16u*16u];
__device__ float  g_buf3[16u*64u*8u*8u*8u];
__device__ float  g_buf4[16u*64u*4u*4u*4u];
__device__ double g_stats[480];
__device__ float  g_scale[5*64];
__device__ float  g_shift[5*64];
__device__ float  g_theta[16*12];
__device__ float  g_wT0[32*16*27];
__device__ float  g_wT1[64*32*27];
__device__ float  g_wT2[64*64*27];

// ---------------- utility kernels ----------------
__global__ void zero_stats_kernel(double* s) {
    int i = threadIdx.x;
    if (i < 480) s[i] = 0.0;
}

__global__ void finalize_kernel(const double* __restrict__ stats,
                                const float* __restrict__ g, const float* __restrict__ be,
                                float* __restrict__ sc, float* __restrict__ sh,
                                int C, double invN) {
    int c = threadIdx.x;
    if (c < C) {
        double mean = stats[c] * invN;
        double var  = stats[C + c] * invN - mean * mean;
        float a = g[c] * (float)(1.0 / sqrt(var + 1e-5));
        sc[c] = a;
        sh[c] = be[c] - (float)mean * a;
    }
}

// weight transpose: w[oc][icr] -> wT[icr][oc]
__global__ void transpose_w_kernel(const float* __restrict__ w, float* __restrict__ wT,
                                   int cin27, int cout) {
    int i = blockIdx.x * 256 + threadIdx.x;
    if (i < cin27 * cout) {
        int oc = i % cout, icr = i / cout;
        wT[i] = w[oc * cin27 + icr];
    }
}

// ---------------- conv00 v2: 1->16 ch, stride 1, pad 1, 64^3, FFMA2 ----------------
__global__ void __launch_bounds__(128) conv00_v2(
    const float* __restrict__ x, const float* __restrict__ w,
    const float* __restrict__ bias, float* __restrict__ out,
    double* __restrict__ stats) {
    __shared__ float sIn[1000];
    __shared__ float sWd[864];

    int tid = threadIdx.x;
    int b = blockIdx.y;
    int t = blockIdx.x;
    int tz = t >> 6, ty = (t >> 3) & 7, tx = t & 7;

    for (int i = tid; i < 1000; i += 128) {
        int iz = i / 100, iy = (i / 10) % 10, ix = i % 10;
        int gz = tz * 8 - 1 + iz, gy = ty * 8 - 1 + iy, gx = tx * 8 - 1 + ix;
        float v = 0.f;
        if ((unsigned)gz < 64u && (unsigned)gy < 64u && (unsigned)gx < 64u)
            v = x[((b * 64 + gz) * 64 + gy) * 64 + gx];
        sIn[i] = v;
    }
    for (int i = tid; i < 432; i += 128) {
        int k = i >> 4, oc = i & 15;
        float wv = w[oc * 27 + k];
        sWd[k * 32 + oc * 2]     = wv;
        sWd[k * 32 + oc * 2 + 1] = wv;
    }
    __syncthreads();

    int sz = tid >> 4, sy = (tid >> 1) & 7, sx = tid & 1;

    u64t acc[16][2];
#pragma unroll
    for (int oc = 0; oc < 16; oc++) { acc[oc][0] = 0ULL; acc[oc][1] = 0ULL; }

#pragma unroll
    for (int kd = 0; kd < 3; kd++)
#pragma unroll
        for (int kh = 0; kh < 3; kh++) {
            int base = (sz + kd) * 100 + (sy + kh) * 10 + sx * 4;
            float i0 = sIn[base], i1 = sIn[base + 1], i2 = sIn[base + 2];
            float i3 = sIn[base + 3], i4 = sIn[base + 4], i5 = sIn[base + 5];
            u64t P[5];
            P[0] = pack2f(i0, i1); P[1] = pack2f(i1, i2); P[2] = pack2f(i2, i3);
            P[3] = pack2f(i3, i4); P[4] = pack2f(i4, i5);
            int k9 = kd * 3 + kh;
#pragma unroll
            for (int kw = 0; kw < 3; kw++) {
                const u64t* wrow =
                    reinterpret_cast<const u64t*>(&sWd[(k9 * 3 + kw) * 32]);
#pragma unroll
                for (int oc = 0; oc < 16; oc++) {
                    u64t wp = wrow[oc];
                    ffma2(acc[oc][0], P[kw], wp);
                    ffma2(acc[oc][1], P[kw + 2], wp);
                }
            }
        }

    int gz = tz * 8 + sz, gy = ty * 8 + sy, gx = tx * 8 + sx * 4;
#pragma unroll 1
    for (int oc = 0; oc < 16; oc++) {
        float a0, a1, a2, a3;
        unpack2f(acc[oc][0], a0, a1);
        unpack2f(acc[oc][1], a2, a3);
        float bb = bias[oc];
        a0 += bb; a1 += bb; a2 += bb; a3 += bb;
        *reinterpret_cast<float4*>(&out[(((b * 16 + oc) * 64 + gz) * 64 + gy) * 64 + gx]) =
            make_float4(a0, a1, a2, a3);

        float s = a0 + a1 + a2 + a3;
        float q = a0 * a0 + a1 * a1 + a2 * a2 + a3 * a3;
#pragma unroll
        for (int off = 16; off > 0; off >>= 1) {
            s += __shfl_down_sync(0xffffffffu, s, off);
            q += __shfl_down_sync(0xffffffffu, q, off);
        }
        if ((tid & 31) == 0) {
            atomicAdd(&stats[oc], (double)s);
            atomicAdd(&stats[16 + oc], (double)q);
        }
    }
}

// ---------------- conv_s2_v7: v6 + software-pipelined input prefetch ---------------
// Slot offsets computed once per block; next c0's input LDGs issue into registers
// right after the STS sync, overlapping the FFMA2 compute phase.
template <int CIN, int COUTT, int COUTB, int OCPT, int ICC, int MAXB>
__global__ void __launch_bounds__(128, MAXB) conv_s2_v7(
    const float* __restrict__ in, const float* __restrict__ wT,
    const float* __restrict__ bias,
    const float* __restrict__ tsc, const float* __restrict__ tsh,
    float* __restrict__ out, double* __restrict__ stats,
    int Din, int Dout, int ntx, int nty) {
    constexpr int GROUPS = COUTB / OCPT;
    constexpr int THREADS = 32 * GROUPS;
    constexpr int NPAIR = OCPT / 2;
    constexpr int IZ = 9, IYE = 9, IX = 17, IXP2 = 18;  // tile 4x4x8 outputs
    constexpr int NINU = ICC * IZ * IYE * IXP2;
    constexpr int NSLOT = (NINU + THREADS - 1) / THREADS;
    constexpr int NW = COUTB * ICC * 27;
    static_assert(THREADS == 128, "tile mapping assumes 128 threads");
    static_assert((NPAIR & 1) == 0, "NPAIR must be even");

    extern __shared__ float sm[];
    u64t*  sInD = reinterpret_cast<u64t*>(sm);
    float* sW   = sm + 2 * NSLOT * THREADS;
    __shared__ float bsum[COUTB], bsq[COUTB];
    __shared__ float sScale[CIN], sShift[CIN];

    int tid = threadIdx.x;
    int b = blockIdx.y;
    int ocBase = blockIdx.z * COUTB;
    int t = blockIdx.x;
    int tx = t % ntx, ty = (t / ntx) % nty, tz = t / (ntx * nty);

    int vt = tid & 31;
    int group = tid >> 5;
    int oxv = vt & 1;
    int oy  = (vt >> 1) & 3;
    int oz  = vt >> 3;

    if (tid < CIN) { sScale[tid] = tsc[tid]; sShift[tid] = tsh[tid]; }

    int ginz = tz * 8 - 1;
    int giny = ty * 8 - 1;
    int ginx = tx * 16 - 1;

    const float* inB = in + (long long)b * CIN * Din * Din * Din;
    const int chanStride = Din * Din * Din;

    // per-slot packed offsets (once per block)
    int goff[NSLOT];
    {
        int i = tid;
#pragma unroll
        for (int s = 0; s < NSLOT; s++, i += THREADS) {
            int ix = i % IXP2;
            int r  = i / IXP2;
            int iy = r % IYE;
            int r2 = r / IYE;
            int iz = r2 % IZ;
            int icl = r2 / IZ;
            int gz = ginz + iz, gy = giny + iy, gx = ginx + ix;
            bool ok = (i < NINU) && (ix < IX) &&
                      ((unsigned)gz < (unsigned)Din) &&
                      ((unsigned)gy < (unsigned)Din) &&
                      ((unsigned)gx < (unsigned)Din);
            int off = ((icl * Din + gz) * Din + gy) * Din + gx;
            goff[s] = ok ? (off | (icl << 24)) : -1;
        }
    }

    u64t acc[NPAIR][4];
#pragma unroll
    for (int p = 0; p < NPAIR; p++)
#pragma unroll
        for (int u = 0; u < 4; u++) acc[p][u] = 0ULL;

    // prologue: prefetch c0=0 input into registers
    float pre[NSLOT];
#pragma unroll
    for (int s = 0; s < NSLOT; s++) {
        int pk = goff[s];
        pre[s] = (pk >= 0) ? __ldg(inB + (pk & 0x00FFFFFF)) : 0.f;
    }

#pragma unroll 1
    for (int c0 = 0; c0 < CIN; c0 += ICC) {
        __syncthreads();   // prev compute done (also covers sScale init at c0=0)
        // input STS from prefetched registers (BN+relu folded)
#pragma unroll
        for (int s = 0; s < NSLOT; s++) {
            int pk = goff[s];
            float v = 0.f;
            if (pk >= 0) {
                int icl = pk >> 24;
                v = fmaxf(fmaf(pre[s], sScale[c0 + icl], sShift[c0 + icl]), 0.f);
            }
            sInD[s * THREADS + tid] = pack2f(v, v);
        }
        // weight load: float4 copy from pre-transposed wT
        {
            const float* srcw = wT + c0 * 27 * COUTT;
            if (COUTB == COUTT) {
#pragma unroll
                for (int i = tid * 4; i < NW; i += THREADS * 4)
                    *reinterpret_cast<float4*>(&sW[i]) =
                        *reinterpret_cast<const float4*>(&srcw[i]);
            } else {
#pragma unroll
                for (int i = tid * 4; i < NW; i += THREADS * 4) {
                    int ocl = i % COUTB;
                    int row = i / COUTB;
                    *reinterpret_cast<float4*>(&sW[i]) =
                        *reinterpret_cast<const float4*>(&srcw[row * COUTT + ocBase + ocl]);
                }
            }
        }
        __syncthreads();

        // prefetch NEXT c0 input (overlaps compute below)
        if (c0 + ICC < CIN) {
            const float* inC2 = inB + (c0 + ICC) * chanStride;
#pragma unroll
            for (int s = 0; s < NSLOT; s++) {
                int pk = goff[s];
                pre[s] = (pk >= 0) ? __ldg(inC2 + (pk & 0x00FFFFFF)) : 0.f;
            }
        }

#pragma unroll
        for (int ic = 0; ic < ICC; ic++) {
#pragma unroll
            for (int kd = 0; kd < 3; kd++)
#pragma unroll
                for (int kh = 0; kh < 3; kh++) {
                    const u64t* ip =
                        &sInD[((ic * IZ + (2 * oz + kd)) * IYE + (2 * oy + kh)) * IXP2 +
                              8 * oxv];
                    ulonglong2 q0 = *reinterpret_cast<const ulonglong2*>(ip);
                    ulonglong2 q1 = *reinterpret_cast<const ulonglong2*>(ip + 2);
                    ulonglong2 q2 = *reinterpret_cast<const ulonglong2*>(ip + 4);
                    ulonglong2 q3 = *reinterpret_cast<const ulonglong2*>(ip + 6);
                    u64t iv8 = ip[8];
                    u64t ivd[9] = {q0.x, q0.y, q1.x, q1.y, q2.x, q2.y, q3.x, q3.y, iv8};
                    int k9 = kd * 3 + kh;
                    const float* wb_ = &sW[(ic * 27 + k9 * 3) * COUTB + group * OCPT];
#pragma unroll
                    for (int kw = 0; kw < 3; kw++) {
                        ulonglong2 wq[NPAIR / 2];
#pragma unroll
                        for (int pp = 0; pp < NPAIR / 2; pp++)
                            wq[pp] = *reinterpret_cast<const ulonglong2*>(
                                wb_ + kw * COUTB + pp * 4);
#pragma unroll
                        for (int u = 0; u < 4; u++) {
                            u64t iv = ivd[2 * u + kw];
#pragma unroll
                            for (int pp = 0; pp < NPAIR / 2; pp++) {
                                ffma2(acc[2 * pp][u], wq[pp].x, iv);
                                ffma2(acc[2 * pp + 1][u], wq[pp].y, iv);
                            }
                        }
                    }
                }
        }
    }

    int gz = tz * 4 + oz, gy = ty * 4 + oy;
    int gx = tx * 8 + oxv * 4;
#pragma unroll 1
    for (int p = 0; p < NPAIR; p++) {
        float o0[4], o1[4];
#pragma unroll
        for (int u = 0; u < 4; u++) unpack2f(acc[p][u], o0[u], o1[u]);
#pragma unroll
        for (int h = 0; h < 2; h++) {
            float* ov = h ? o1 : o0;
            int ocl = group * OCPT + 2 * p + h;
            int oc = ocBase + ocl;
            float bb = bias[oc];
            float a0 = ov[0] + bb, a1 = ov[1] + bb, a2 = ov[2] + bb, a3 = ov[3] + bb;
            *reinterpret_cast<float4*>(
                &out[(((b * COUTT + oc) * Dout + gz) * Dout + gy) * Dout + gx]) =
                make_float4(a0, a1, a2, a3);

            float s = a0 + a1 + a2 + a3;
            float q = a0 * a0 + a1 * a1 + a2 * a2 + a3 * a3;
#pragma unroll
            for (int off = 16; off > 0; off >>= 1) {
                s += __shfl_down_sync(0xffffffffu, s, off);
                q += __shfl_down_sync(0xffffffffu, q, off);
            }
            if (vt == 0) { bsum[ocl] = s; bsq[ocl] = q; }
        }
    }
    __syncthreads();
    if (tid < COUTB) {
        atomicAdd(&stats[ocBase + tid], (double)bsum[tid]);
        atomicAdd(&stats[COUTT + ocBase + tid], (double)bsq[tid]);
    }
}

// ---------------- old generic stride-2 conv (kept for tiny stage 4) ----------------
template <int CIN, int COUTB, int OCPT>
__global__ void __launch_bounds__(128) conv_s2_kernel(
    const float* __restrict__ in, const float* __restrict__ w,
    const float* __restrict__ bias,
    const float* __restrict__ tsc, const float* __restrict__ tsh,
    float* __restrict__ out, double* __restrict__ stats,
    int Din, int Dout, int ntile, int coutTot) {
    constexpr int ICC = 16;
    constexpr int NIN = ICC * 729;
    constexpr int NW  = COUTB * ICC * 27;
    extern __shared__ float sm[];
    float* sIn = sm;
    float* sW  = sm + NIN;
    __shared__ float bsum[COUTB], bsq[COUTB];

    int tid = threadIdx.x;
    int b = blockIdx.y;
    int ocBase = blockIdx.z * COUTB;
    int t = blockIdx.x;
    int tz = t / (ntile * ntile), ty = (t / ntile) % ntile, tx = t % ntile;
    int pair = tid & 31, group = tid >> 5;
    int oz = pair >> 3, oy = (pair >> 1) & 3, px = pair & 1;

    if (tid < COUTB) { bsum[tid] = 0.f; bsq[tid] = 0.f; }

    float acc0[OCPT], acc1[OCPT];
#pragma unroll
    for (int j = 0; j < OCPT; j++) { acc0[j] = 0.f; acc1[j] = 0.f; }

    for (int c0 = 0; c0 < CIN; c0 += ICC) {
        __syncthreads();
        for (int i = tid; i < NIN; i += 128) {
            int ic = i / 729, r = i % 729;
            int iz = r / 81, iy = (r / 9) % 9, ix = r % 9;
            int gz = tz * 8 - 1 + iz, gy = ty * 8 - 1 + iy, gx = tx * 8 - 1 + ix;
            float v = 0.f;
            if ((unsigned)gz < (unsigned)Din && (unsigned)gy < (unsigned)Din &&
                (unsigned)gx < (unsigned)Din) {
                v = in[(((b * CIN + c0 + ic) * Din + gz) * Din + gy) * Din + gx];
                v = fmaxf(fmaf(v, tsc[c0 + ic], tsh[c0 + ic]), 0.f);
            }
            sIn[i] = v;
        }
        for (int i = tid; i < NW; i += 128) {
            int ocl = i / (ICC * 27), r = i % (ICC * 27);
            sW[i] = w[((ocBase + ocl) * CIN + c0) * 27 + r];
        }
        __syncthreads();

#pragma unroll 1
        for (int ic = 0; ic < ICC; ic++) {
            const float* wrow = &sW[(group * OCPT) * ICC * 27 + ic * 27];
#pragma unroll
            for (int kd = 0; kd < 3; kd++)
#pragma unroll
                for (int kh = 0; kh < 3; kh++) {
                    int base = ((ic * 9 + (2 * oz + kd)) * 9 + (2 * oy + kh)) * 9 + 4 * px;
                    float ivs[5];
#pragma unroll
                    for (int u = 0; u < 5; u++) ivs[u] = sIn[base + u];
#pragma unroll
                    for (int kw = 0; kw < 3; kw++) {
#pragma unroll
                        for (int j = 0; j < OCPT; j++) {
                            float wv = wrow[j * ICC * 27 + (kd * 3 + kh) * 3 + kw];
                            acc0[j] = fmaf(ivs[kw], wv, acc0[j]);
                            acc1[j] = fmaf(ivs[kw + 2], wv, acc1[j]);
                        }
                    }
                }
        }
    }

    int gz = tz * 4 + oz, gy = ty * 4 + oy, gx = tx * 4 + 2 * px;
#pragma unroll
    for (int j = 0; j < OCPT; j++) {
        int oc = ocBase + group * OCPT + j;
        float bb = bias[oc];
        float o0 = acc0[j] + bb, o1 = acc1[j] + bb;
        *reinterpret_cast<float2*>(
            &out[(((b * coutTot + oc) * Dout + gz) * Dout + gy) * Dout + gx]) =
            make_float2(o0, o1);

        float s = o0 + o1, q = o0 * o0 + o1 * o1;
#pragma unroll
        for (int off = 16; off > 0; off >>= 1) {
            s += __shfl_down_sync(0xffffffffu, s, off);
            q += __shfl_down_sync(0xffffffffu, q, off);
        }
        if (pair == 0) {
            atomicAdd(&bsum[group * OCPT + j], s);
            atomicAdd(&bsq[group * OCPT + j], q);
        }
    }
    __syncthreads();
    if (tid < COUTB) {
        atomicAdd(&stats[ocBase + tid], (double)bsum[tid]);
        atomicAdd(&stats[coutTot + ocBase + tid], (double)bsq[tid]);
    }
}

// ---------------- heads: 12 dot products + affine matrix composition ----------------
__device__ __forceinline__ void ident4(float* M) {
#pragma unroll
    for (int i = 0; i < 16; i++) M[i] = (i % 5 == 0) ? 1.f : 0.f;
}
__device__ __forceinline__ void mm4(const float* A, const float* B, float* C) {
#pragma unroll
    for (int i = 0; i < 4; i++)
#pragma unroll
        for (int j = 0; j < 4; j++)
            C[i * 4 + j] = A[i * 4 + 0] * B[0 + j] + A[i * 4 + 1] * B[4 + j] +
                           A[i * 4 + 2] * B[8 + j] + A[i * 4 + 3] * B[12 + j];
}

__global__ void __launch_bounds__(256) heads_kernel(
    const float* __restrict__ xs, const float* __restrict__ sc, const float* __restrict__ sh,
    const float* __restrict__ tw, const float* __restrict__ tb,
    const float* __restrict__ rw, const float* __restrict__ rb,
    const float* __restrict__ sw_, const float* __restrict__ sb_,
    const float* __restrict__ shw, const float* __restrict__ shb,
    float* __restrict__ theta) {
    __shared__ float red[12 * 256];
    int b = blockIdx.x, tid = threadIdx.x;
    float p[12];
#pragma unroll
    for (int r = 0; r < 12; r++) p[r] = 0.f;
    for (int i = tid; i < 4096; i += 256) {
        int c = i >> 6;
        float v = fmaxf(fmaf(xs[b * 4096 + i], sc[c], sh[c]), 0.f);
#pragma unroll
        for (int r = 0; r < 3; r++) {
            p[r]     = fmaf(v, tw[r * 4096 + i], p[r]);
            p[3 + r] = fmaf(v, rw[r * 4096 + i], p[3 + r]);
            p[6 + r] = fmaf(v, sw_[r * 4096 + i], p[6 + r]);
            p[9 + r] = fmaf(v, shw[r * 4096 + i], p[9 + r]);
        }
    }
#pragma unroll
    for (int r = 0; r < 12; r++) red[r * 256 + tid] = p[r];
    __syncthreads();
    for (int s = 128; s > 0; s >>= 1) {
        if (tid < s)
#pragma unroll
            for (int r = 0; r < 12; r++) red[r * 256 + tid] += red[r * 256 + tid + s];
        __syncthreads();
    }
    if (tid == 0) {
        const float PI4 = 0.7853981633974483f;
        float tr[3], ro[3], scp[3], shp[3];
#pragma unroll
        for (int r = 0; r < 3; r++) {
            tr[r]  = tanhf(red[r * 256] + tb[r]) * 0.1f;
            ro[r]  = tanhf(red[(3 + r) * 256] + rb[r]) * PI4;
            scp[r] = tanhf(red[(6 + r) * 256] + sb_[r]) * 0.2f;
            shp[r] = tanhf(red[(9 + r) * 256] + shb[r]) * PI4;
        }
        float c0 = cosf(ro[0]), s0 = sinf(ro[0]);
        float c1 = cosf(ro[1]), s1 = sinf(ro[1]);
        float c2 = cosf(ro[2]), s2 = sinf(ro[2]);
        float cs0 = cosf(shp[0]), ss0 = sinf(shp[0]);
        float cs1 = cosf(shp[1]), ss1 = sinf(shp[1]);
        float cs2 = cosf(shp[2]), ss2 = sinf(shp[2]);

        float T[16], R1[16], R2[16], R3[16], S[16], H1[16], H2[16], H3[16];
        float R[16], Sh[16], ShT[16], A[16], B[16];
        ident4(T);  T[3] = tr[0]; T[7] = tr[1]; T[11] = tr[2];
        ident4(R1); R1[0] = c0; R1[1] = -s0; R1[4] = s0; R1[5] = c0;
        ident4(R2); R2[5] = c1; R2[6] = -s1; R2[9] = s1; R2[10] = c1;
        ident4(R3); R3[0] = c2; R3[1] = -s2; R3[4] = s2; R3[5] = c2;
        ident4(S);  S[0] = expf(scp[0]); S[5] = expf(scp[1]); S[10] = expf(scp[2]);
        ident4(H1); H1[5] = cs0; H1[6] = -ss0; H1[9] = ss0; H1[10] = cs0;
        ident4(H2); H2[0] = cs1; H2[2] = ss1; H2[8] = -ss1; H2[10] = cs1;
        ident4(H3); H3[0] = cs2; H3[1] = -ss2; H3[4] = ss2; H3[5] = cs2;

        mm4(R1, R2, A); mm4(A, R3, R);
        mm4(H1, H2, A); mm4(A, H3, Sh);
#pragma unroll
        for (int i = 0; i < 4; i++)
#pragma unroll
            for (int j = 0; j < 4; j++) ShT[i * 4 + j] = Sh[j * 4 + i];
        mm4(Sh, S, A); mm4(A, ShT, B); mm4(B, R, A); mm4(A, T, B);
#pragma unroll
        for (int i = 0; i < 12; i++) theta[b * 12 + i] = B[i];
    }
}

// ---------------- trilinear grid sample (zero padding, clamped gather) ----------------
__global__ void __launch_bounds__(256) sampler_kernel(
    const float* __restrict__ x, const float* __restrict__ theta,
    float* __restrict__ out) {
    int idx = blockIdx.x * 256 + threadIdx.x;
    int b = idx >> 18;
    int r = idx & 262143;
    int z = r >> 12, y = (r >> 6) & 63, xq = r & 63;
    const float st = 2.f / 63.f;
    float xx = fmaf((float)xq, st, -1.f);
    float yy = fmaf((float)y, st, -1.f);
    float zz = fmaf((float)z, st, -1.f);
    const float* th = &theta[b * 12];
    float g0 = th[0] * xx + th[1] * yy + th[2] * zz + th[3];
    float g1 = th[4] * xx + th[5] * yy + th[6] * zz + th[7];
    float g2 = th[8] * xx + th[9] * yy + th[10] * zz + th[11];
    float fx = ((g0 + 1.f) * 64.f - 1.f) * 0.5f;
    float fy = ((g1 + 1.f) * 64.f - 1.f) * 0.5f;
    float fz = ((g2 + 1.f) * 64.f - 1.f) * 0.5f;
    float x0f = floorf(fx), y0f = floorf(fy), z0f = floorf(fz);
    int x0 = (int)x0f, y0 = (int)y0f, z0 = (int)z0f;
    float wx1 = fx - x0f, wx0 = 1.f - wx1;
    float wy1 = fy - y0f, wy0 = 1.f - wy1;
    float wz1 = fz - z0f, wz0 = 1.f - wz1;
    const float* xb = &x[b << 18];
    float acc = 0.f;
#pragma unroll
    for (int dz = 0; dz < 2; dz++) {
        int zc = z0 + dz;
        float wz = dz ? wz1 : wz0;
        bool vz = (zc >= 0 && zc < 64);
        int zi = min(max(zc, 0), 63);
#pragma unroll
        for (int dy = 0; dy < 2; dy++) {
            int yc = y0 + dy;
            float wy = dy ? wy1 : wy0;
            bool vy = vz && (yc >= 0 && yc < 64);
            int yi = min(max(yc, 0), 63);
#pragma unroll
            for (int dx = 0; dx < 2; dx++) {
                int xc = x0 + dx;
                float wgt = wz * wy * (dx ? wx1 : wx0);
                bool v = vy && (xc >= 0 && xc < 64);
                int xi = min(max(xc, 0), 63);
                float val = xb[(zi * 64 + yi) * 64 + xi];
                acc += v ? val * wgt : 0.f;
            }
        }
    }
    out[idx] = acc;
}

// ---------------- launch ----------------
extern "C" void kernel_launch(void* const* d_in, const int* in_sizes, int n_in,
                              void* d_out, int out_size) {
    const float* x    = (const float*)d_in[0];
    const float* w00  = (const float*)d_in[1];
    const float* b00  = (const float*)d_in[2];
    const float* g00  = (const float*)d_in[3];
    const float* be00 = (const float*)d_in[4];
    const float* w0   = (const float*)d_in[5];
    const float* b0   = (const float*)d_in[6];
    const float* g0   = (const float*)d_in[7];
    const float* be0  = (const float*)d_in[8];
    const float* w1   = (const float*)d_in[9];
    const float* b1   = (const float*)d_in[10];
    const float* g1   = (const float*)d_in[11];
    const float* be1  = (const float*)d_in[12];
    const float* w2   = (const float*)d_in[13];
    const float* b2   = (const float*)d_in[14];
    const float* g2   = (const float*)d_in[15];
    const float* be2  = (const float*)d_in[16];
    const float* w3   = (const float*)d_in[17];
    const float* b3   = (const float*)d_in[18];
    const float* g3   = (const float*)d_in[19];
    const float* be3  = (const float*)d_in[20];
    const float* tw   = (const float*)d_in[21];
    const float* tb   = (const float*)d_in[22];
    const float* rw   = (const float*)d_in[23];
    const float* rb   = (const float*)d_in[24];
    const float* sw   = (const float*)d_in[25];
    const float* sb   = (const float*)d_in[26];
    const float* shw  = (const float*)d_in[27];
    const float* shb  = (const float*)d_in[28];

    float *buf0, *buf1, *buf2, *buf3, *buf4, *scale, *shift, *theta;
    float *wT0, *wT1, *wT2;
    double* stats;
    cudaGetSymbolAddress((void**)&buf0, g_buf0);
    cudaGetSymbolAddress((void**)&buf1, g_buf1);
    cudaGetSymbolAddress((void**)&buf2, g_buf2);
    cudaGetSymbolAddress((void**)&buf3, g_buf3);
    cudaGetSymbolAddress((void**)&buf4, g_buf4);
    cudaGetSymbolAddress((void**)&stats, g_stats);
    cudaGetSymbolAddress((void**)&scale, g_scale);
    cudaGetSymbolAddress((void**)&shift, g_shift);
    cudaGetSymbolAddress((void**)&theta, g_theta);
    cudaGetSymbolAddress((void**)&wT0, g_wT0);
    cudaGetSymbolAddress((void**)&wT1, g_wT1);
    cudaGetSymbolAddress((void**)&wT2, g_wT2);

    // NSLOT = 23 -> input smem 23*128*8 = 23552 B
    const int SM_S1  = 23 * 128 * 8 + 32 * 2 * 27 * 4;  // 30464
    const int SM_S2  = 23 * 128 * 8 + 64 * 2 * 27 * 4;  // 37376
    const int SM_S3  = 23 * 128 * 8 + 32 * 2 * 27 * 4;  // 30464 (COUTB=32 split)
    const int SM_L3OLD = (16 * 729 + 16 * 16 * 27) * 4; // 74304 (stage 4)
    cudaFuncSetAttribute(conv_s2_v7<16, 32, 32, 8, 2, 4>,
                         cudaFuncAttributeMaxDynamicSharedMemorySize, SM_S1);
    cudaFuncSetAttribute(conv_s2_v7<32, 64, 64, 16, 2, 3>,
                         cudaFuncAttributeMaxDynamicSharedMemorySize, SM_S2);
    cudaFuncSetAttribute(conv_s2_v7<64, 64, 32, 8, 2, 4>,
                         cudaFuncAttributeMaxDynamicSharedMemorySize, SM_S3);
    cudaFuncSetAttribute(conv_s2_kernel<64, 16, 4>,
                         cudaFuncAttributeMaxDynamicSharedMemorySize, SM_L3OLD);

    zero_stats_kernel<<<1, 512>>>(stats);

    // one-shot weight transposes
    transpose_w_kernel<<<(32 * 16 * 27 + 255) / 256, 256>>>(w0, wT0, 16 * 27, 32);
    transpose_w_kernel<<<(64 * 32 * 27 + 255) / 256, 256>>>(w1, wT1, 32 * 27, 64);
    transpose_w_kernel<<<(64 * 64 * 27 + 255) / 256, 256>>>(w2, wT2, 64 * 27, 64);

    // stage 0: conv00 1->16, 64^3 (FFMA2)
    conv00_v2<<<dim3(512, 16), 128>>>(x, w00, b00, buf0, stats + 0);
    finalize_kernel<<<1, 64>>>(stats + 0, g00, be00, scale + 0, shift + 0, 16,
                               1.0 / 4194304.0);

    // stage 1: 16->32, 64^3 -> 32^3; 256 tiles (ntx=4, nty=8)
    conv_s2_v7<16, 32, 32, 8, 2, 4><<<dim3(256, 16, 1), 128, SM_S1>>>(
        buf0, wT0, b0, scale + 0, shift + 0, buf1, stats + 32, 64, 32, 4, 8);
    finalize_kernel<<<1, 64>>>(stats + 32, g0, be0, scale + 64, shift + 64, 32,
                               1.0 / 524288.0);

    // stage 2: 32->64, 32^3 -> 16^3; 32 tiles (ntx=2, nty=4), full 64 oc
    conv_s2_v7<32, 64, 64, 16, 2, 3><<<dim3(32, 16, 1), 128, SM_S2>>>(
        buf1, wT1, b1, scale + 64, shift + 64, buf2, stats + 96, 32, 16, 2, 4);
    finalize_kernel<<<1, 64>>>(stats + 96, g1, be1, scale + 128, shift + 128, 64,
                               1.0 / 65536.0);

    // stage 3: 64->64, 16^3 -> 8^3; 4 tiles (ntx=1, nty=2), oc split z=2
    conv_s2_v7<64, 64, 32, 8, 2, 4><<<dim3(4, 16, 2), 128, SM_S3>>>(
        buf2, wT2, b2, scale + 128, shift + 128, buf3, stats + 224, 16, 8, 1, 2);
    finalize_kernel<<<1, 64>>>(stats + 224, g2, be2, scale + 192, shift + 192, 64,
                               1.0 / 8192.0);

    // stage 4: 64->64, 8^3 -> 4^3 (tiny; old kernel, oc split into 4 z-blocks)
    conv_s2_kernel<64, 16, 4><<<dim3(1, 16, 4), 128, SM_L3OLD>>>(
        buf3, w3, b3, scale + 192, shift + 192, buf4, stats + 352, 8, 4, 1, 64);
    finalize_kernel<<<1, 64>>>(stats + 352, g3, be3, scale + 256, shift + 256, 64,
                               1.0 / 1024.0);

    // heads + affine composition
    heads_kernel<<<16, 256>>>(buf4, scale + 256, shift + 256, tw, tb, rw, rb, sw, sb,
                              shw, shb, theta);

    // grid sample
    sampler_kernel<<<16384, 256>>>(x, theta, (float*)d_out);
}